// round 1
// baseline (speedup 1.0000x reference)
#include <cuda_runtime.h>
#include <math.h>

// ---------------- problem constants (match reference setup) ----------------
#define MAXN 50000
#define MAXE 800000
#define D 64

// ---------------- scratch (static device globals; no allocs) ---------------
__device__ float g_xn  [MAXN * D];   // layernormed x
__device__ float g_q   [MAXN * D];   // per-node query
__device__ float g_v   [MAXE * D];   // per-edge value
__device__ float g_att [MAXE];       // per-edge attention logit
__device__ float g_max [MAXN];       // segment max
__device__ float g_den [MAXN];       // segment sum of exp
__device__ float g_aggr[MAXN * D];   // aggregated output

__device__ __forceinline__ float gelu_erf(float x) {
    return 0.5f * x * (1.0f + erff(x * 0.70710678118654752440f));
}

// float atomic max via signed/unsigned int ordering trick
__device__ __forceinline__ void atomicMaxFloat(float* addr, float val) {
    if (val >= 0.0f) atomicMax((int*)addr, __float_as_int(val));
    else             atomicMin((unsigned int*)addr, __float_as_uint(val));
}

// warp GEMV: out[m] = b[m] + sum_c WT[c*64+m] * in[c], lane owns m=lane, m=lane+32
__device__ __forceinline__ void gemv64(const float* __restrict__ WT,
                                       float in0, float in1,
                                       float b0, float b1,
                                       int lane, float& o0, float& o1) {
    float a0 = b0, a1 = b1;
#pragma unroll
    for (int c = 0; c < 32; c++) {
        float xv = __shfl_sync(0xffffffffu, in0, c);
        a0 += WT[c * 64 + lane]      * xv;
        a1 += WT[c * 64 + 32 + lane] * xv;
    }
#pragma unroll
    for (int c = 0; c < 32; c++) {
        float xv = __shfl_sync(0xffffffffu, in1, c);
        a0 += WT[(c + 32) * 64 + lane]      * xv;
        a1 += WT[(c + 32) * 64 + 32 + lane] * xv;
    }
    o0 = a0; o1 = a1;
}

// ---------------- kernel 0: init scratch --------------------------------
__global__ void init_kernel(int N) {
    int i = blockIdx.x * blockDim.x + threadIdx.x;
    if (i < N * D) g_aggr[i] = 0.0f;
    if (i < N) { g_max[i] = -INFINITY; g_den[i] = 0.0f; }
}

// ---------------- kernel 1: layernorm + per-node q ------------------------
__global__ __launch_bounds__(256) void node_kernel(
    const float* __restrict__ x, const float* __restrict__ gamma,
    const float* __restrict__ beta, const float* __restrict__ Wq,
    const float* __restrict__ bq, int N)
{
    __shared__ float sWqT[64 * 64];
    __shared__ float sbq[64], sg[64], sb[64];
    int tid = threadIdx.x;
    for (int i = tid; i < 64 * 64; i += blockDim.x) {
        int c = i >> 6, m = i & 63;
        sWqT[i] = Wq[m * 64 + c];
    }
    if (tid < 64) { sbq[tid] = bq[tid]; sg[tid] = gamma[tid]; sb[tid] = beta[tid]; }
    __syncthreads();

    int lane = tid & 31;
    int warp = (blockIdx.x * blockDim.x + tid) >> 5;
    int nw   = (gridDim.x * blockDim.x) >> 5;
    for (int n = warp; n < N; n += nw) {
        float x0 = x[n * 64 + lane];
        float x1 = x[n * 64 + 32 + lane];
        float s = x0 + x1;
#pragma unroll
        for (int o = 16; o; o >>= 1) s += __shfl_xor_sync(0xffffffffu, s, o);
        float mu = s * (1.0f / 64.0f);
        float d0 = x0 - mu, d1 = x1 - mu;
        float vs = d0 * d0 + d1 * d1;
#pragma unroll
        for (int o = 16; o; o >>= 1) vs += __shfl_xor_sync(0xffffffffu, vs, o);
        float inv = rsqrtf(vs * (1.0f / 64.0f) + 1e-5f);
        float xn0 = d0 * inv * sg[lane]      + sb[lane];
        float xn1 = d1 * inv * sg[lane + 32] + sb[lane + 32];
        g_xn[n * 64 + lane]      = xn0;
        g_xn[n * 64 + 32 + lane] = xn1;
        float q0, q1;
        gemv64(sWqT, xn0, xn1, sbq[lane], sbq[lane + 32], lane, q0, q1);
        g_q[n * 64 + lane]      = q0;
        g_q[n * 64 + 32 + lane] = q1;
    }
}

// ---------------- kernel 2: fused edge xt / k / att / v -------------------
// dyn smem layout (floats): WtT(65*64) WksT WkdT WvsT WvdT(4096 each)
//                           bt bks bkd bvs bvd (64 each) div(64)
#define EDGE_SMEM_FLOATS (65*64 + 4*4096 + 5*64 + 64)

__global__ __launch_bounds__(256) void edge_main_kernel(
    const int* __restrict__ ei, const float* __restrict__ etime,
    const float* __restrict__ esame,
    const float* __restrict__ Wt,  const float* __restrict__ bt,
    const float* __restrict__ Wks, const float* __restrict__ bks,
    const float* __restrict__ Wkd, const float* __restrict__ bkd,
    const float* __restrict__ Wvs, const float* __restrict__ bvs,
    const float* __restrict__ Wvd, const float* __restrict__ bvd,
    int E)
{
    extern __shared__ float sm[];
    float* sWtT  = sm;                  // 65*64 (row c=0..64 of input dim, col m)
    float* sWksT = sWtT  + 65 * 64;
    float* sWkdT = sWksT + 4096;
    float* sWvsT = sWkdT + 4096;
    float* sWvdT = sWvsT + 4096;
    float* sB    = sWvdT + 4096;        // bt | bks | bkd | bvs | bvd
    float* sDiv  = sB + 5 * 64;

    int tid = threadIdx.x;
    for (int i = tid; i < 65 * 64; i += blockDim.x) {
        int c = i >> 6, m = i & 63;
        sWtT[i] = Wt[m * 65 + c];
    }
    for (int i = tid; i < 4096; i += blockDim.x) {
        int c = i >> 6, m = i & 63;
        sWksT[i] = Wks[m * 64 + c];
        sWkdT[i] = Wkd[m * 64 + c];
        sWvsT[i] = Wvs[m * 64 + c];
        sWvdT[i] = Wvd[m * 64 + c];
    }
    for (int i = tid; i < 64; i += blockDim.x) {
        sB[i]       = bt[i];
        sB[64 + i]  = bks[i];
        sB[128 + i] = bkd[i];
        sB[192 + i] = bvs[i];
        sB[256 + i] = bvd[i];
        sDiv[i] = powf(10000.0f, -(float)(2 * (i / 2)) / 64.0f);
    }
    __syncthreads();

    int lane = tid & 31;
    int warp = (blockIdx.x * blockDim.x + tid) >> 5;
    int nw   = (gridDim.x * blockDim.x) >> 5;

    for (int e = warp; e < E; e += nw) {
        int src = ei[e];
        int dst = ei[E + e];
        float t = etime[e];
        bool same = (esame[e] >= 0.5f);

        float xj0 = g_xn[src * 64 + lane];
        float xj1 = g_xn[src * 64 + 32 + lane];

        // xt = gelu([xj, t] @ Wt^T + bt) + te
        float a0 = sB[lane]      + sWtT[64 * 64 + lane]      * t;
        float a1 = sB[lane + 32] + sWtT[64 * 64 + lane + 32] * t;
#pragma unroll
        for (int c = 0; c < 32; c++) {
            float xv = __shfl_sync(0xffffffffu, xj0, c);
            a0 += sWtT[c * 64 + lane]      * xv;
            a1 += sWtT[c * 64 + 32 + lane] * xv;
        }
#pragma unroll
        for (int c = 0; c < 32; c++) {
            float xv = __shfl_sync(0xffffffffu, xj1, c);
            a0 += sWtT[(c + 32) * 64 + lane]      * xv;
            a1 += sWtT[(c + 32) * 64 + 32 + lane] * xv;
        }
        float t200 = t * 200.0f;
        float pe0 = t200 * sDiv[lane];
        float pe1 = t200 * sDiv[lane + 32];
        float te0 = (lane & 1) ? cosf(pe0) : sinf(pe0);
        float te1 = (lane & 1) ? cosf(pe1) : sinf(pe1);   // (lane+32) parity == lane parity
        float xt0 = gelu_erf(a0) + te0;
        float xt1 = gelu_erf(a1) + te1;

        // k = xt @ Wk^T + bk (exact select since es in {0,1})
        const float* WkT = same ? sWksT : sWkdT;
        const float* bk  = same ? (sB + 64) : (sB + 128);
        float k0, k1;
        gemv64(WkT, xt0, xt1, bk[lane], bk[lane + 32], lane, k0, k1);

        // att = dot(k, q[dst]) / 8
        float q0 = g_q[dst * 64 + lane];
        float q1 = g_q[dst * 64 + 32 + lane];
        float p = k0 * q0 + k1 * q1;
#pragma unroll
        for (int o = 16; o; o >>= 1) p += __shfl_xor_sync(0xffffffffu, p, o);
        float att = p * 0.125f;

        // v = xt @ Wv^T + bv
        const float* WvT = same ? sWvsT : sWvdT;
        const float* bv  = same ? (sB + 192) : (sB + 256);
        float v0, v1;
        gemv64(WvT, xt0, xt1, bv[lane], bv[lane + 32], lane, v0, v1);
        g_v[(size_t)e * 64 + lane]      = v0;
        g_v[(size_t)e * 64 + 32 + lane] = v1;

        if (lane == 0) {
            g_att[e] = att;
            atomicMaxFloat(&g_max[dst], att);
        }
    }
}

// ---------------- kernel 3: softmax denominator ---------------------------
__global__ void denom_kernel(const int* __restrict__ ei, int E) {
    int e = blockIdx.x * blockDim.x + threadIdx.x;
    if (e >= E) return;
    int dst = ei[E + e];
    float m = g_max[dst];
    if (!isfinite(m)) m = 0.0f;
    atomicAdd(&g_den[dst], expf(g_att[e] - m));
}

// ---------------- kernel 4: weighted scatter of v -------------------------
__global__ __launch_bounds__(256) void scatter_kernel(const int* __restrict__ ei, int E) {
    int lane = threadIdx.x & 31;
    int warp = (blockIdx.x * blockDim.x + threadIdx.x) >> 5;
    if (warp >= E) return;
    int e = warp;
    int dst = ei[E + e];
    float m = g_max[dst];
    if (!isfinite(m)) m = 0.0f;
    float attn = expf(g_att[e] - m) / (g_den[dst] + 1e-16f);
    float v0 = g_v[(size_t)e * 64 + lane];
    float v1 = g_v[(size_t)e * 64 + 32 + lane];
    atomicAdd(&g_aggr[dst * 64 + lane],      attn * v0);
    atomicAdd(&g_aggr[dst * 64 + 32 + lane], attn * v1);
}

// ---------------- kernel 5: epilogue --------------------------------------
__global__ void final_kernel(const float* __restrict__ x, float* __restrict__ out, int N) {
    int i = blockIdx.x * blockDim.x + threadIdx.x;
    if (i < N * D) out[i] = x[i] + gelu_erf(g_aggr[i]);
}

// ---------------- launch ---------------------------------------------------
extern "C" void kernel_launch(void* const* d_in, const int* in_sizes, int n_in,
                              void* d_out, int out_size) {
    const float* x     = (const float*)d_in[0];
    const int*   ei    = (const int*)  d_in[1];
    const float* etime = (const float*)d_in[2];
    // d_in[3] = x_time (unused by reference)
    const float* esame = (const float*)d_in[4];
    const float* lng   = (const float*)d_in[5];
    const float* lnb   = (const float*)d_in[6];
    const float* Wt    = (const float*)d_in[7];
    const float* bt    = (const float*)d_in[8];
    const float* Wq    = (const float*)d_in[9];
    const float* bq    = (const float*)d_in[10];
    const float* Wks   = (const float*)d_in[11];
    const float* bks   = (const float*)d_in[12];
    const float* Wkd   = (const float*)d_in[13];
    const float* bkd   = (const float*)d_in[14];
    const float* Wvs   = (const float*)d_in[15];
    const float* bvs   = (const float*)d_in[16];
    const float* Wvd   = (const float*)d_in[17];
    const float* bvd   = (const float*)d_in[18];
    float* out = (float*)d_out;

    int N = in_sizes[0] / D;
    int E = in_sizes[2];
    if (N > MAXN) N = MAXN;
    if (E > MAXE) E = MAXE;

    const int smem_bytes = EDGE_SMEM_FLOATS * (int)sizeof(float);
    cudaFuncSetAttribute(edge_main_kernel,
                         cudaFuncAttributeMaxDynamicSharedMemorySize, smem_bytes);

    init_kernel<<<(N * D + 255) / 256, 256>>>(N);
    node_kernel<<<(N + 7) / 8, 256>>>(x, lng, lnb, Wq, bq, N);
    edge_main_kernel<<<296, 256, smem_bytes>>>(ei, etime, esame,
                                               Wt, bt, Wks, bks, Wkd, bkd,
                                               Wvs, bvs, Wvd, bvd, E);
    denom_kernel<<<(E + 255) / 256, 256>>>(ei, E);
    scatter_kernel<<<(E + 7) / 8, 256>>>(ei, E);
    final_kernel<<<(N * D + 255) / 256, 256>>>(x, out, N);
}

// round 2
// speedup vs baseline: 2.4286x; 2.4286x over previous
#include <cuda_runtime.h>
#include <math.h>

#define MAXN 50000
#define MAXE 800000
#define D 64

typedef unsigned long long ull;

// ---------------- scratch ---------------------------------------------------
__device__ float g_xn  [MAXN * D];
__device__ float g_qh_s[MAXN * D];   // (q @ Wks) per node
__device__ float g_qh_d[MAXN * D];   // (q @ Wkd) per node
__device__ float g_c_s [MAXN];       // bks . q
__device__ float g_c_d [MAXN];       // bkd . q
__device__ float g_v   [MAXE * D];
__device__ float g_att [MAXE];
__device__ float g_max [MAXN];
__device__ float g_den [MAXN];
__device__ float g_aggr[MAXN * D];
__device__ int   g_perm_s[MAXE];
__device__ int   g_perm_d[MAXE];
__device__ int   g_cnt[2];

__device__ __forceinline__ float gelu_erf(float x) {
    return 0.5f * x * (1.0f + erff(x * 0.70710678118654752440f));
}

__device__ __forceinline__ void atomicMaxFloat(float* addr, float val) {
    if (val >= 0.0f) atomicMax((int*)addr, __float_as_int(val));
    else             atomicMin((unsigned int*)addr, __float_as_uint(val));
}

__device__ __forceinline__ ull dup2(float x) {
    ull r; asm("mov.b64 %0, {%1, %1};" : "=l"(r) : "f"(x)); return r;
}
__device__ __forceinline__ void ffma2(ull& d, ull a, ull b) {
    asm("fma.rn.f32x2 %0, %1, %2, %0;" : "+l"(d) : "l"(a), "l"(b));
}
__device__ __forceinline__ float2 unpk(ull v) {
    float2 f; asm("mov.b64 {%0, %1}, %2;" : "=f"(f.x), "=f"(f.y) : "l"(v)); return f;
}

// warp GEMV: out[m] = b[m] + sum_c WT[c*64+m] * in[c]
__device__ __forceinline__ void gemv64(const float* __restrict__ WT,
                                       float in0, float in1,
                                       float b0, float b1,
                                       int lane, float& o0, float& o1) {
    float a0 = b0, a1 = b1;
#pragma unroll
    for (int c = 0; c < 32; c++) {
        float xv = __shfl_sync(0xffffffffu, in0, c);
        a0 += WT[c * 64 + lane]      * xv;
        a1 += WT[c * 64 + 32 + lane] * xv;
    }
#pragma unroll
    for (int c = 0; c < 32; c++) {
        float xv = __shfl_sync(0xffffffffu, in1, c);
        a0 += WT[(c + 32) * 64 + lane]      * xv;
        a1 += WT[(c + 32) * 64 + 32 + lane] * xv;
    }
    o0 = a0; o1 = a1;
}

// ---------------- kernel 0: init -------------------------------------------
__global__ void init_kernel(int N) {
    int i = blockIdx.x * blockDim.x + threadIdx.x;
    if (i < N * D) g_aggr[i] = 0.0f;
    if (i < N) { g_max[i] = -INFINITY; g_den[i] = 0.0f; }
    if (i == 0) { g_cnt[0] = 0; g_cnt[1] = 0; }
}

// ---------------- kernel 0b: partition edges by edge_same ------------------
__global__ void partition_kernel(const float* __restrict__ esame, int E) {
    int e = blockIdx.x * blockDim.x + threadIdx.x;
    if (e >= E) return;
    if (esame[e] >= 0.5f) { int p = atomicAdd(&g_cnt[0], 1); g_perm_s[p] = e; }
    else                  { int p = atomicAdd(&g_cnt[1], 1); g_perm_d[p] = e; }
}

// ---------------- kernel 1: layernorm + node-side precompute ----------------
#define NODE_SMEM_FLOATS (3 * 4096 + 5 * 64)
__global__ __launch_bounds__(256) void node_kernel(
    const float* __restrict__ x, const float* __restrict__ gamma,
    const float* __restrict__ beta,
    const float* __restrict__ Wq, const float* __restrict__ bq,
    const float* __restrict__ Wks, const float* __restrict__ bks,
    const float* __restrict__ Wkd, const float* __restrict__ bkd,
    int N)
{
    extern __shared__ float ns[];
    float* sWqT = ns;            // [c][m] = Wq[m][c]
    float* sWks = ns + 4096;     // raw
    float* sWkd = ns + 8192;     // raw
    float* sbq  = ns + 12288;
    float* sg   = sbq + 64;
    float* sb   = sg + 64;
    float* sbks = sb + 64;
    float* sbkd = sbks + 64;

    int tid = threadIdx.x;
    for (int i = tid; i < 4096; i += 256) {
        int m = i >> 6, c = i & 63;
        sWqT[c * 64 + m] = Wq[i];
        sWks[i] = Wks[i];
        sWkd[i] = Wkd[i];
    }
    if (tid < 64) {
        sbq[tid] = bq[tid]; sg[tid] = gamma[tid]; sb[tid] = beta[tid];
        sbks[tid] = bks[tid]; sbkd[tid] = bkd[tid];
    }
    __syncthreads();

    int lane = tid & 31;
    int warp = (blockIdx.x * blockDim.x + tid) >> 5;
    int nw   = (gridDim.x * blockDim.x) >> 5;
    for (int n = warp; n < N; n += nw) {
        float x0 = x[n * 64 + lane];
        float x1 = x[n * 64 + 32 + lane];
        float s = x0 + x1;
#pragma unroll
        for (int o = 16; o; o >>= 1) s += __shfl_xor_sync(0xffffffffu, s, o);
        float mu = s * (1.0f / 64.0f);
        float d0 = x0 - mu, d1 = x1 - mu;
        float vs = d0 * d0 + d1 * d1;
#pragma unroll
        for (int o = 16; o; o >>= 1) vs += __shfl_xor_sync(0xffffffffu, vs, o);
        float inv = rsqrtf(vs * (1.0f / 64.0f) + 1e-5f);
        float xn0 = d0 * inv * sg[lane]      + sb[lane];
        float xn1 = d1 * inv * sg[lane + 32] + sb[lane + 32];
        g_xn[n * 64 + lane]      = xn0;
        g_xn[n * 64 + 32 + lane] = xn1;

        float q0, q1;
        gemv64(sWqT, xn0, xn1, sbq[lane], sbq[lane + 32], lane, q0, q1);

        // qh = q @ Wk  (out[c] = sum_m Wk[m][c]*q[m])
        float h0, h1;
        gemv64(sWks, q0, q1, 0.0f, 0.0f, lane, h0, h1);
        g_qh_s[n * 64 + lane] = h0; g_qh_s[n * 64 + 32 + lane] = h1;
        gemv64(sWkd, q0, q1, 0.0f, 0.0f, lane, h0, h1);
        g_qh_d[n * 64 + lane] = h0; g_qh_d[n * 64 + 32 + lane] = h1;

        float cs = q0 * sbks[lane] + q1 * sbks[lane + 32];
        float cd = q0 * sbkd[lane] + q1 * sbkd[lane + 32];
#pragma unroll
        for (int o = 16; o; o >>= 1) {
            cs += __shfl_xor_sync(0xffffffffu, cs, o);
            cd += __shfl_xor_sync(0xffffffffu, cd, o);
        }
        if (lane == 0) { g_c_s[n] = cs; g_c_d[n] = cd; }
    }
}

// ---------------- kernel 2: tiled edge GEMM (xt -> att, v) ------------------
// 128 edges/CTA, 128 threads, 8x8 micro-tile, f32x2 packed FMA.
#define EDGE_SMEM_FLOATS (65*128 + 65*64 + 64*64 + 128*8 + 128 + 64 + 64 + 64 + 128 + 128)

__global__ __launch_bounds__(128, 3) void edge_kernel(
    const int* __restrict__ ei, const float* __restrict__ etime,
    const float* __restrict__ Wt,  const float* __restrict__ bt,
    const float* __restrict__ Wvs, const float* __restrict__ bvs,
    const float* __restrict__ Wvd, const float* __restrict__ bvd,
    int E)
{
    extern __shared__ float sm[];
    float* XsT  = sm;                  // [65][128]  (k-major x, reused as xtT)
    float* W1s  = XsT + 65 * 128;      // [65][64]   Wt^T
    float* W2s  = W1s + 65 * 64;       // [64][64]   Wv^T (selected)
    float* patt = W2s + 64 * 64;       // [128][8]
    float* st   = patt + 128 * 8;      // [128] times
    float* sdiv = st + 128;            // [64]
    float* sbt  = sdiv + 64;           // [64]
    float* sbv  = sbt + 64;            // [64]
    int*   sperm = (int*)(sbv + 64);   // [128]
    int*   sdst  = sperm + 128;        // [128]

    int tid = threadIdx.x;
    int bid = blockIdx.x;

    int cs = g_cnt[0];
    int ts = (cs + 127) >> 7;
    const int* list; int off, cnt, same;
    if (bid < ts) {
        list = g_perm_s; off = bid << 7; cnt = min(128, cs - off); same = 1;
    } else {
        int cd = g_cnt[1];
        off = (bid - ts) << 7;
        if (off >= cd) return;
        list = g_perm_d; cnt = min(128, cd - off); same = 0;
    }
    const float* Wv = same ? Wvs : Wvd;
    const float* bv = same ? bvs : bvd;
    const float* qh = same ? g_qh_s : g_qh_d;
    const float* cv = same ? g_c_s  : g_c_d;

    // ---- prologue: weights (coalesced read, transposed store) ----
    for (int i = tid; i < 65 * 64; i += 128) {
        int m = i / 65, k = i % 65;
        W1s[k * 64 + m] = Wt[i];
    }
    for (int i = tid; i < 64 * 64; i += 128) {
        int m = i >> 6, k = i & 63;
        W2s[k * 64 + m] = Wv[i];
    }
    if (tid < 64) {
        sbt[tid] = bt[tid];
        sbv[tid] = bv[tid];
        sdiv[tid] = powf(10000.0f, -(float)(2 * (tid >> 1)) / 64.0f);
    }

    // ---- gather 128 edge rows (transposed) ----
    {
        int e = tid;
        bool act = e < cnt;
        int pe = 0, src = 0, dstn = 0; float tt = 0.0f;
        if (act) { pe = list[off + e]; src = ei[pe]; dstn = ei[E + pe]; tt = etime[pe]; }
        sperm[e] = pe; sdst[e] = dstn; st[e] = tt;
        const float4* xr = (const float4*)(g_xn + (size_t)src * 64);
#pragma unroll
        for (int kk = 0; kk < 16; kk++) {
            float4 v = act ? xr[kk] : make_float4(0.f, 0.f, 0.f, 0.f);
            XsT[(4 * kk + 0) * 128 + e] = v.x;
            XsT[(4 * kk + 1) * 128 + e] = v.y;
            XsT[(4 * kk + 2) * 128 + e] = v.z;
            XsT[(4 * kk + 3) * 128 + e] = v.w;
        }
        XsT[64 * 128 + e] = tt;
    }
    __syncthreads();

    int ty = tid >> 3, tx = tid & 7;
    int row0 = ty << 3, col0 = tx << 3;

    // ---- GEMM1: xt = X(128x65) @ W1s(65x64), acc pairs over edges ----
    ull acc[32];
#pragma unroll
    for (int j = 0; j < 8; j++) {
        ull bd = dup2(sbt[col0 + j]);
        acc[j] = bd; acc[8 + j] = bd; acc[16 + j] = bd; acc[24 + j] = bd;
    }
#pragma unroll 5
    for (int k = 0; k < 65; k++) {
        const ull* ap = (const ull*)(XsT + k * 128 + row0);
        ull a0 = ap[0], a1 = ap[1], a2 = ap[2], a3 = ap[3];
        const float* bp = W1s + k * 64 + col0;
        float4 b0 = *(const float4*)bp, b1 = *(const float4*)(bp + 4);
        float bb[8] = {b0.x, b0.y, b0.z, b0.w, b1.x, b1.y, b1.z, b1.w};
#pragma unroll
        for (int j = 0; j < 8; j++) {
            ull bd = dup2(bb[j]);
            ffma2(acc[j],      a0, bd);
            ffma2(acc[8 + j],  a1, bd);
            ffma2(acc[16 + j], a2, bd);
            ffma2(acc[24 + j], a3, bd);
        }
    }
    __syncthreads();   // everyone done reading XsT before reuse as xtT

    // ---- epilogue1: gelu + temporal enc; att partials; store xtT ----
    float* xtT = XsT;
    float pa[8] = {0, 0, 0, 0, 0, 0, 0, 0};
#pragma unroll
    for (int i2 = 0; i2 < 4; i2++) {
        int e0 = row0 + 2 * i2, e1 = e0 + 1;
        float t0 = st[e0] * 200.0f, t1 = st[e1] * 200.0f;
        const float4* q0p = (const float4*)(qh + (size_t)sdst[e0] * 64 + col0);
        const float4* q1p = (const float4*)(qh + (size_t)sdst[e1] * 64 + col0);
        float4 qa = q0p[0], qb = q0p[1], qc = q1p[0], qd = q1p[1];
        float qv0[8] = {qa.x, qa.y, qa.z, qa.w, qb.x, qb.y, qb.z, qb.w};
        float qv1[8] = {qc.x, qc.y, qc.z, qc.w, qd.x, qd.y, qd.z, qd.w};
#pragma unroll
        for (int j2 = 0; j2 < 4; j2++) {
            float dv = sdiv[col0 + 2 * j2];
            float s0, c0, s1, c1;
            sincosf(t0 * dv, &s0, &c0);
            sincosf(t1 * dv, &s1, &c1);
            float2 ue = unpk(acc[i2 * 8 + 2 * j2]);
            float2 uo = unpk(acc[i2 * 8 + 2 * j2 + 1]);
            float x00 = gelu_erf(ue.x) + s0;   // e0, even col -> sin
            float x10 = gelu_erf(ue.y) + s1;   // e1, even col
            float x01 = gelu_erf(uo.x) + c0;   // e0, odd col -> cos
            float x11 = gelu_erf(uo.y) + c1;   // e1, odd col
            pa[2 * i2]     += x00 * qv0[2 * j2] + x01 * qv0[2 * j2 + 1];
            pa[2 * i2 + 1] += x10 * qv1[2 * j2] + x11 * qv1[2 * j2 + 1];
            *(float2*)(xtT + (col0 + 2 * j2) * 128 + e0)     = make_float2(x00, x10);
            *(float2*)(xtT + (col0 + 2 * j2 + 1) * 128 + e0) = make_float2(x01, x11);
        }
    }
#pragma unroll
    for (int i = 0; i < 8; i++) patt[(row0 + i) * 8 + tx] = pa[i];
    __syncthreads();

    // ---- att reduce + writes ----
    {
        int e = tid;
        if (e < cnt) {
            float s = 0.0f;
#pragma unroll
            for (int j = 0; j < 8; j++) s += patt[e * 8 + j];
            int dn = sdst[e];
            float att = (s + cv[dn]) * 0.125f;
            g_att[sperm[e]] = att;
            atomicMaxFloat(&g_max[dn], att);
        }
    }

    // ---- GEMM2: v = xt(128x64) @ W2s(64x64), acc pairs over cols ----
    ull acc2[32];   // [i][j2]
    {
        const ull* bvp = (const ull*)(sbv + col0);
        ull w0 = bvp[0], w1 = bvp[1], w2 = bvp[2], w3 = bvp[3];
#pragma unroll
        for (int i = 0; i < 8; i++) {
            acc2[i * 4] = w0; acc2[i * 4 + 1] = w1; acc2[i * 4 + 2] = w2; acc2[i * 4 + 3] = w3;
        }
    }
#pragma unroll 4
    for (int k = 0; k < 64; k++) {
        const float4* axp = (const float4*)(xtT + k * 128 + row0);
        float4 a0 = axp[0], a1 = axp[1];
        float aa[8] = {a0.x, a0.y, a0.z, a0.w, a1.x, a1.y, a1.z, a1.w};
        const ull* bp = (const ull*)(W2s + k * 64 + col0);
        ull w0 = bp[0], w1 = bp[1], w2 = bp[2], w3 = bp[3];
#pragma unroll
        for (int i = 0; i < 8; i++) {
            ull ad = dup2(aa[i]);
            ffma2(acc2[i * 4],     ad, w0);
            ffma2(acc2[i * 4 + 1], ad, w1);
            ffma2(acc2[i * 4 + 2], ad, w2);
            ffma2(acc2[i * 4 + 3], ad, w3);
        }
    }
#pragma unroll
    for (int i = 0; i < 8; i++) {
        int e = row0 + i;
        if (e < cnt) {
            float* dp = g_v + (size_t)sperm[e] * 64 + col0;
            float2 v0 = unpk(acc2[i * 4]),     v1 = unpk(acc2[i * 4 + 1]);
            float2 v2 = unpk(acc2[i * 4 + 2]), v3 = unpk(acc2[i * 4 + 3]);
            *(float4*)dp       = make_float4(v0.x, v0.y, v1.x, v1.y);
            *(float4*)(dp + 4) = make_float4(v2.x, v2.y, v3.x, v3.y);
        }
    }
}

// ---------------- kernel 3: softmax denominator -----------------------------
__global__ void denom_kernel(const int* __restrict__ ei, int E) {
    int e = blockIdx.x * blockDim.x + threadIdx.x;
    if (e >= E) return;
    int dst = ei[E + e];
    float m = g_max[dst];
    if (!isfinite(m)) m = 0.0f;
    atomicAdd(&g_den[dst], expf(g_att[e] - m));
}

// ---------------- kernel 4: weighted scatter (vector red) -------------------
__global__ __launch_bounds__(256) void scatter_kernel(const int* __restrict__ ei, int E) {
    int idx = blockIdx.x * 256 + threadIdx.x;
    int e = idx >> 4;
    if (e >= E) return;
    int p = idx & 15;
    int dst = ei[E + e];
    float m = g_max[dst];
    if (!isfinite(m)) m = 0.0f;
    float attn = expf(g_att[e] - m) / (g_den[dst] + 1e-16f);
    float4 v = *(const float4*)(g_v + (size_t)e * 64 + p * 4);
    float* addr = g_aggr + (size_t)dst * 64 + p * 4;
    asm volatile("red.global.add.v4.f32 [%0], {%1, %2, %3, %4};"
                 :: "l"(addr), "f"(attn * v.x), "f"(attn * v.y),
                    "f"(attn * v.z), "f"(attn * v.w) : "memory");
}

// ---------------- kernel 5: epilogue ----------------------------------------
__global__ void final_kernel(const float* __restrict__ x, float* __restrict__ out, int N) {
    int i = blockIdx.x * blockDim.x + threadIdx.x;
    if (i < N * D) out[i] = x[i] + gelu_erf(g_aggr[i]);
}

// ---------------- launch -----------------------------------------------------
extern "C" void kernel_launch(void* const* d_in, const int* in_sizes, int n_in,
                              void* d_out, int out_size) {
    const float* x     = (const float*)d_in[0];
    const int*   ei    = (const int*)  d_in[1];
    const float* etime = (const float*)d_in[2];
    const float* esame = (const float*)d_in[4];
    const float* lng   = (const float*)d_in[5];
    const float* lnb   = (const float*)d_in[6];
    const float* Wt    = (const float*)d_in[7];
    const float* bt    = (const float*)d_in[8];
    const float* Wq    = (const float*)d_in[9];
    const float* bq    = (const float*)d_in[10];
    const float* Wks   = (const float*)d_in[11];
    const float* bks   = (const float*)d_in[12];
    const float* Wkd   = (const float*)d_in[13];
    const float* bkd   = (const float*)d_in[14];
    const float* Wvs   = (const float*)d_in[15];
    const float* bvs   = (const float*)d_in[16];
    const float* Wvd   = (const float*)d_in[17];
    const float* bvd   = (const float*)d_in[18];
    float* out = (float*)d_out;

    int N = in_sizes[0] / D;
    int E = in_sizes[2];
    if (N > MAXN) N = MAXN;
    if (E > MAXE) E = MAXE;

    const int node_smem = NODE_SMEM_FLOATS * (int)sizeof(float);
    const int edge_smem = EDGE_SMEM_FLOATS * (int)sizeof(float);
    cudaFuncSetAttribute(node_kernel, cudaFuncAttributeMaxDynamicSharedMemorySize, node_smem);
    cudaFuncSetAttribute(edge_kernel, cudaFuncAttributeMaxDynamicSharedMemorySize, edge_smem);

    init_kernel<<<(N * D + 255) / 256, 256>>>(N);
    partition_kernel<<<(E + 255) / 256, 256>>>(esame, E);
    node_kernel<<<(N + 7) / 8, 256, node_smem>>>(x, lng, lnb, Wq, bq, Wks, bks, Wkd, bkd, N);
    edge_kernel<<<(E + 127) / 128 + 1, 128, edge_smem>>>(ei, etime, Wt, bt,
                                                         Wvs, bvs, Wvd, bvd, E);
    denom_kernel<<<(E + 255) / 256, 256>>>(ei, E);
    scatter_kernel<<<(E * 16 + 255) / 256, 256>>>(ei, E);
    final_kernel<<<(N * D + 255) / 256, 256>>>(x, out, N);
}

// round 4
// speedup vs baseline: 2.6622x; 1.0962x over previous
#include <cuda_runtime.h>
#include <math.h>

#define MAXN 50000
#define MAXE 800000
#define D 64
#define XS 130   // XsT row stride (bank-conflict pad, keeps 8B align)
#define WS 68    // weight smem row stride (bank pad, keeps 16B align)
#define XSZ (65*XS + 2)   // pad +2 so region after XsT is 16B-aligned

typedef unsigned long long ull;

// ---------------- scratch ---------------------------------------------------
__device__ float g_xn  [MAXN * D];
__device__ float g_qh_s[MAXN * D];
__device__ float g_qh_d[MAXN * D];
__device__ float g_c_s [MAXN];
__device__ float g_c_d [MAXN];
__device__ float g_v   [MAXE * D];
__device__ float g_att [MAXE];
__device__ float g_max [MAXN];
__device__ float g_den [MAXN];
__device__ float g_aggr[MAXN * D];
__device__ int   g_perm_s[MAXE];
__device__ int   g_perm_d[MAXE];
__device__ int   g_cnt[2];
// folded weights
__device__ float g_MsT[4096];   // [j][c] = sum_m Wks[m][c]*Wq[m][j]
__device__ float g_MdT[4096];
__device__ float g_ds[64], g_dd[64];   // Wk^T bq
__device__ float g_us[64], g_ud[64];   // bk^T Wq
__device__ float g_ec[2];              // bk . bq

__device__ __forceinline__ float gelu_erf(float x) {
    return 0.5f * x * (1.0f + erff(x * 0.70710678118654752440f));
}
__device__ __forceinline__ void atomicMaxFloat(float* addr, float val) {
    if (val >= 0.0f) atomicMax((int*)addr, __float_as_int(val));
    else             atomicMin((unsigned int*)addr, __float_as_uint(val));
}
__device__ __forceinline__ ull dup2(float x) {
    ull r; asm("mov.b64 %0, {%1, %1};" : "=l"(r) : "f"(x)); return r;
}
__device__ __forceinline__ void ffma2(ull& d, ull a, ull b) {
    asm("fma.rn.f32x2 %0, %1, %2, %0;" : "+l"(d) : "l"(a), "l"(b));
}
__device__ __forceinline__ float2 unpk(ull v) {
    float2 f; asm("mov.b64 {%0, %1}, %2;" : "=f"(f.x), "=f"(f.y) : "l"(v)); return f;
}

// ---------------- kernel 0: init --------------------------------------------
__global__ void init_kernel(int N) {
    int i = blockIdx.x * blockDim.x + threadIdx.x;
    if (i < N * D) g_aggr[i] = 0.0f;
    if (i < N) { g_max[i] = -INFINITY; g_den[i] = 0.0f; }
    if (i == 0) { g_cnt[0] = 0; g_cnt[1] = 0; }
}

// ---------------- kernel 0b: partition edges by edge_same -------------------
__global__ void partition_kernel(const float* __restrict__ esame, int E) {
    int e = blockIdx.x * blockDim.x + threadIdx.x;
    if (e >= E) return;
    if (esame[e] >= 0.5f) { int p = atomicAdd(&g_cnt[0], 1); g_perm_s[p] = e; }
    else                  { int p = atomicAdd(&g_cnt[1], 1); g_perm_d[p] = e; }
}

// ---------------- kernel 0c: fold Wq into Wk space ---------------------------
__global__ __launch_bounds__(256) void fold_kernel(
    const float* __restrict__ Wq, const float* __restrict__ bq,
    const float* __restrict__ Wk, const float* __restrict__ bk,
    float* __restrict__ MT, float* __restrict__ dvec,
    float* __restrict__ uvec, float* __restrict__ evec)
{
    __shared__ float sWq[4096], sWk[4096], sbq[64], sbk[64];
    int tid = threadIdx.x;
    for (int i = tid; i < 4096; i += 256) { sWq[i] = Wq[i]; sWk[i] = Wk[i]; }
    if (tid < 64) { sbq[tid] = bq[tid]; sbk[tid] = bk[tid]; }
    __syncthreads();
#pragma unroll
    for (int ii = 0; ii < 16; ii++) {
        int o = tid + ii * 256;
        int j = o >> 6, c = o & 63;
        float s = 0.0f;
#pragma unroll 8
        for (int m = 0; m < 64; m++) s += sWk[m * 64 + c] * sWq[m * 64 + j];
        MT[o] = s;
    }
    if (tid < 64) {
        float sd = 0.0f, su = 0.0f;
#pragma unroll 8
        for (int m = 0; m < 64; m++) {
            sd += sWk[m * 64 + tid] * sbq[m];
            su += sbk[m] * sWq[m * 64 + tid];
        }
        dvec[tid] = sd; uvec[tid] = su;
    }
    if (tid == 0) {
        float s = 0.0f;
        for (int m = 0; m < 64; m++) s += sbk[m] * sbq[m];
        *evec = s;
    }
}

// ---------------- kernel 1: layernorm + qh_s/qh_d/c --------------------------
#define NODE_SMEM_FLOATS (64*XS + 2*64*WS + 8*64)
__global__ __launch_bounds__(256, 2) void node_kernel(
    const float* __restrict__ x, const float* __restrict__ gamma,
    const float* __restrict__ beta, int N)
{
    extern __shared__ float ns[];
    float* XsT = ns;                    // [64][XS]  (64*130=8320 fl, 16B-mult)
    float* sMs = XsT + 64 * XS;        // [64][WS]
    float* sMd = sMs + 64 * WS;
    float* sg  = sMd + 64 * WS;
    float* sb  = sg + 64;
    float* sus = sb + 64;
    float* sud = sus + 64;
    float* sds = sud + 64;
    float* sdd = sds + 64;

    int tid = threadIdx.x;
    for (int i = tid; i < 4096; i += 256) {
        int j = i >> 6, c = i & 63;
        sMs[j * WS + c] = g_MsT[i];
        sMd[j * WS + c] = g_MdT[i];
    }
    if (tid < 64) {
        sg[tid] = gamma[tid]; sb[tid] = beta[tid];
        sus[tid] = g_us[tid]; sud[tid] = g_ud[tid];
        sds[tid] = g_ds[tid]; sdd[tid] = g_dd[tid];
    }
    __syncthreads();

    int n0 = blockIdx.x * 128;
    int cnt = min(128, N - n0);

    // ---- LN gather: 2 threads per node ----
    {
        int nl = tid >> 1, half = tid & 1;
        bool act = nl < cnt;
        int n = n0 + nl;
        float4 xv[8];
        float s = 0.0f, t = 0.0f;
        if (act) {
            const float4* xr = (const float4*)(x + (size_t)n * 64) + half * 8;
#pragma unroll
            for (int kk = 0; kk < 8; kk++) {
                xv[kk] = xr[kk];
                s += xv[kk].x + xv[kk].y + xv[kk].z + xv[kk].w;
                t += xv[kk].x * xv[kk].x + xv[kk].y * xv[kk].y
                   + xv[kk].z * xv[kk].z + xv[kk].w * xv[kk].w;
            }
        }
        s += __shfl_xor_sync(0xffffffffu, s, 1);
        t += __shfl_xor_sync(0xffffffffu, t, 1);
        float mu = s * (1.0f / 64.0f);
        float var = t * (1.0f / 64.0f) - mu * mu;
        float inv = rsqrtf(var + 1e-5f);
        float cs = 0.0f, cd = 0.0f;
        if (act) {
            float* gx = g_xn + (size_t)n * 64 + half * 32;
#pragma unroll
            for (int kk = 0; kk < 8; kk++) {
                int c0 = half * 32 + 4 * kk;
                float v[4] = {xv[kk].x, xv[kk].y, xv[kk].z, xv[kk].w};
                float xn4[4];
#pragma unroll
                for (int p = 0; p < 4; p++) {
                    int c = c0 + p;
                    float xn = (v[p] - mu) * inv * sg[c] + sb[c];
                    xn4[p] = xn;
                    XsT[c * XS + nl] = xn;
                    cs += xn * sus[c];
                    cd += xn * sud[c];
                }
                *(float4*)(gx + 4 * kk) = make_float4(xn4[0], xn4[1], xn4[2], xn4[3]);
            }
        }
        cs += __shfl_xor_sync(0xffffffffu, cs, 1);
        cd += __shfl_xor_sync(0xffffffffu, cd, 1);
        if (act && half == 0) {
            g_c_s[n] = cs + g_ec[0];
            g_c_d[n] = cd + g_ec[1];
        }
    }
    __syncthreads();

    // ---- two GEMMs: qh = XsT^T @ M + d ----
    int ty = tid >> 3, tx = tid & 7;
    int row0 = ty << 2, col0 = tx << 3;
#pragma unroll
    for (int pass = 0; pass < 2; pass++) {
        const float* M = pass ? sMd : sMs;
        const float* dv = pass ? sdd : sds;
        float* outp = pass ? g_qh_d : g_qh_s;
        ull acc[16];
        {
            const ull* dp = (const ull*)(dv + col0);
            ull w0 = dp[0], w1 = dp[1], w2 = dp[2], w3 = dp[3];
#pragma unroll
            for (int i = 0; i < 4; i++) {
                acc[i * 4] = w0; acc[i * 4 + 1] = w1; acc[i * 4 + 2] = w2; acc[i * 4 + 3] = w3;
            }
        }
#pragma unroll 4
        for (int k = 0; k < 64; k++) {
            const ull* axp = (const ull*)(XsT + k * XS + row0);
            float2 f01 = unpk(axp[0]), f23 = unpk(axp[1]);
            float aa[4] = {f01.x, f01.y, f23.x, f23.y};
            const ull* bp = (const ull*)(M + k * WS + col0);
            ull w0 = bp[0], w1 = bp[1], w2 = bp[2], w3 = bp[3];
#pragma unroll
            for (int i = 0; i < 4; i++) {
                ull ad = dup2(aa[i]);
                ffma2(acc[i * 4],     ad, w0);
                ffma2(acc[i * 4 + 1], ad, w1);
                ffma2(acc[i * 4 + 2], ad, w2);
                ffma2(acc[i * 4 + 3], ad, w3);
            }
        }
#pragma unroll
        for (int i = 0; i < 4; i++) {
            int nl = row0 + i;
            if (nl < cnt) {
                float* dp = outp + (size_t)(n0 + nl) * 64 + col0;
                float2 v0 = unpk(acc[i * 4]),     v1 = unpk(acc[i * 4 + 1]);
                float2 v2 = unpk(acc[i * 4 + 2]), v3 = unpk(acc[i * 4 + 3]);
                *(float4*)dp       = make_float4(v0.x, v0.y, v1.x, v1.y);
                *(float4*)(dp + 4) = make_float4(v2.x, v2.y, v3.x, v3.y);
            }
        }
    }
}

// ---------------- kernel 2: tiled edge GEMM (xt -> att, v) -------------------
#define EDGE_SMEM_FLOATS (XSZ + 65*WS + 128 + 64 + 64 + 64 + 128 + 128)

__global__ __launch_bounds__(256, 2) void edge_kernel(
    const int* __restrict__ ei, const float* __restrict__ etime,
    const float* __restrict__ Wt,  const float* __restrict__ bt,
    const float* __restrict__ Wvs, const float* __restrict__ bvs,
    const float* __restrict__ Wvd, const float* __restrict__ bvd,
    int E)
{
    extern __shared__ float sm[];
    float* XsT  = sm;                  // [65][XS], reused as xtT
    float* Ws   = XsT + XSZ;           // [65][WS] (16B-aligned: XSZ=8452)
    float* st   = Ws + 65 * WS;        // [128]
    float* sdiv = st + 128;            // [64]
    float* sbt  = sdiv + 64;           // [64]
    float* sbv  = sbt + 64;            // [64]
    int* sperm  = (int*)(sbv + 64);    // [128]
    int* sdst   = sperm + 128;         // [128]

    int tid = threadIdx.x;
    int bid = blockIdx.x;

    int cs = g_cnt[0];
    int ts = (cs + 127) >> 7;
    const int* list; int off, cnt, same;
    if (bid < ts) {
        list = g_perm_s; off = bid << 7; cnt = min(128, cs - off); same = 1;
    } else {
        int cd = g_cnt[1];
        off = (bid - ts) << 7;
        if (off >= cd) return;
        list = g_perm_d; cnt = min(128, cd - off); same = 0;
    }
    const float* Wv = same ? Wvs : Wvd;
    const float* bv = same ? bvs : bvd;
    const float* qh = same ? g_qh_s : g_qh_d;
    const float* cv = same ? g_c_s  : g_c_d;

    // ---- prologue: W1 (transposed), biases, gather X (2 thr/edge) ----
    for (int i = tid; i < 65 * 64; i += 256) {
        int m = i / 65, k = i % 65;
        Ws[k * WS + m] = Wt[i];
    }
    if (tid < 64) {
        sbt[tid] = bt[tid];
        sbv[tid] = bv[tid];
        sdiv[tid] = powf(10000.0f, -(float)(2 * (tid >> 1)) / 64.0f);
    }
    {
        int el = tid >> 1, half = tid & 1;
        bool act = el < cnt;
        int pe = 0, src = 0, dstn = 0; float tt = 0.0f;
        if (act) { pe = list[off + el]; src = ei[pe]; dstn = ei[E + pe]; tt = etime[pe]; }
        if (half == 0) {
            sperm[el] = pe; sdst[el] = dstn; st[el] = tt;
            XsT[64 * XS + el] = tt;
        }
        const float4* xr = (const float4*)(g_xn + (size_t)src * 64) + half * 8;
#pragma unroll
        for (int kk = 0; kk < 8; kk++) {
            float4 v = act ? xr[kk] : make_float4(0.f, 0.f, 0.f, 0.f);
            int c0 = half * 32 + 4 * kk;
            XsT[(c0 + 0) * XS + el] = v.x;
            XsT[(c0 + 1) * XS + el] = v.y;
            XsT[(c0 + 2) * XS + el] = v.z;
            XsT[(c0 + 3) * XS + el] = v.w;
        }
    }
    __syncthreads();

    int ty = tid >> 3, tx = tid & 7;
    int row0 = ty << 2, col0 = tx << 3;

    // ---- GEMM1: xt_pre = X(128x65) @ W1(65x64); acc packs edge pairs ----
    ull acc[16];   // acc[j]: edges (row0,row0+1); acc[8+j]: (row0+2,row0+3)
#pragma unroll
    for (int j = 0; j < 8; j++) {
        ull bd = dup2(sbt[col0 + j]);
        acc[j] = bd; acc[8 + j] = bd;
    }
#pragma unroll 5
    for (int k = 0; k < 65; k++) {
        const ull* ap = (const ull*)(XsT + k * XS + row0);
        ull a0 = ap[0], a1 = ap[1];
        const float* bp = Ws + k * WS + col0;
        float4 b0 = *(const float4*)bp, b1 = *(const float4*)(bp + 4);
        float bb[8] = {b0.x, b0.y, b0.z, b0.w, b1.x, b1.y, b1.z, b1.w};
#pragma unroll
        for (int j = 0; j < 8; j++) {
            ull bd = dup2(bb[j]);
            ffma2(acc[j],     a0, bd);
            ffma2(acc[8 + j], a1, bd);
        }
    }
    __syncthreads();   // done reading XsT / Ws

    // ---- start W2 load into registers (coalesced) ----
    float w2r[16];
#pragma unroll
    for (int ii = 0; ii < 16; ii++) w2r[ii] = Wv[tid + ii * 256];

    // ---- epilogue1: gelu + temporal enc; att partials; store xtT ----
    float* xtT = XsT;
    float pa[4] = {0, 0, 0, 0};
#pragma unroll
    for (int i2 = 0; i2 < 2; i2++) {
        int e0 = row0 + 2 * i2, e1 = e0 + 1;
        float t0 = st[e0] * 200.0f, t1 = st[e1] * 200.0f;
        const float4* q0p = (const float4*)(qh + (size_t)sdst[e0] * 64 + col0);
        const float4* q1p = (const float4*)(qh + (size_t)sdst[e1] * 64 + col0);
        float4 qa = q0p[0], qb = q0p[1], qc = q1p[0], qd = q1p[1];
        float qv0[8] = {qa.x, qa.y, qa.z, qa.w, qb.x, qb.y, qb.z, qb.w};
        float qv1[8] = {qc.x, qc.y, qc.z, qc.w, qd.x, qd.y, qd.z, qd.w};
#pragma unroll
        for (int j2 = 0; j2 < 4; j2++) {
            float dv = sdiv[col0 + 2 * j2];
            float s0, c0, s1, c1;
            sincosf(t0 * dv, &s0, &c0);
            sincosf(t1 * dv, &s1, &c1);
            float2 ue = unpk(acc[i2 * 8 + 2 * j2]);
            float2 uo = unpk(acc[i2 * 8 + 2 * j2 + 1]);
            float x00 = gelu_erf(ue.x) + s0;
            float x10 = gelu_erf(ue.y) + s1;
            float x01 = gelu_erf(uo.x) + c0;
            float x11 = gelu_erf(uo.y) + c1;
            pa[2 * i2]     += x00 * qv0[2 * j2] + x01 * qv0[2 * j2 + 1];
            pa[2 * i2 + 1] += x10 * qv1[2 * j2] + x11 * qv1[2 * j2 + 1];
            *(float2*)(xtT + (col0 + 2 * j2) * XS + e0)     = make_float2(x00, x10);
            *(float2*)(xtT + (col0 + 2 * j2 + 1) * XS + e0) = make_float2(x01, x11);
        }
    }
    // att: shuffle-reduce over the 8 tx lanes
#pragma unroll
    for (int o = 4; o; o >>= 1) {
#pragma unroll
        for (int i = 0; i < 4; i++) pa[i] += __shfl_xor_sync(0xffffffffu, pa[i], o);
    }
    if (tx < 4) {
        int e = row0 + tx;
        if (e < cnt) {
            int dn = sdst[e];
            float att = (pa[tx] + cv[dn]) * 0.125f;
            g_att[sperm[e]] = att;
            atomicMaxFloat(&g_max[dn], att);
        }
    }
    // ---- store W2 (transposed) ----
#pragma unroll
    for (int ii = 0; ii < 16; ii++) {
        int i = tid + ii * 256;
        int m = i >> 6, k = i & 63;
        Ws[k * WS + m] = w2r[ii];
    }
    __syncthreads();

    // ---- GEMM2: v = xt(128x64) @ W2(64x64); acc packs col pairs ----
    ull acc2[16];
    {
        const ull* bvp = (const ull*)(sbv + col0);
        ull w0 = bvp[0], w1 = bvp[1], w2 = bvp[2], w3 = bvp[3];
#pragma unroll
        for (int i = 0; i < 4; i++) {
            acc2[i * 4] = w0; acc2[i * 4 + 1] = w1; acc2[i * 4 + 2] = w2; acc2[i * 4 + 3] = w3;
        }
    }
#pragma unroll 4
    for (int k = 0; k < 64; k++) {
        const ull* axp = (const ull*)(xtT + k * XS + row0);
        float2 f01 = unpk(axp[0]), f23 = unpk(axp[1]);
        float aa[4] = {f01.x, f01.y, f23.x, f23.y};
        const ull* bp = (const ull*)(Ws + k * WS + col0);
        ull w0 = bp[0], w1 = bp[1], w2 = bp[2], w3 = bp[3];
#pragma unroll
        for (int i = 0; i < 4; i++) {
            ull ad = dup2(aa[i]);
            ffma2(acc2[i * 4],     ad, w0);
            ffma2(acc2[i * 4 + 1], ad, w1);
            ffma2(acc2[i * 4 + 2], ad, w2);
            ffma2(acc2[i * 4 + 3], ad, w3);
        }
    }
#pragma unroll
    for (int i = 0; i < 4; i++) {
        int e = row0 + i;
        if (e < cnt) {
            float* dp = g_v + (size_t)sperm[e] * 64 + col0;
            float2 v0 = unpk(acc2[i * 4]),     v1 = unpk(acc2[i * 4 + 1]);
            float2 v2 = unpk(acc2[i * 4 + 2]), v3 = unpk(acc2[i * 4 + 3]);
            *(float4*)dp       = make_float4(v0.x, v0.y, v1.x, v1.y);
            *(float4*)(dp + 4) = make_float4(v2.x, v2.y, v3.x, v3.y);
        }
    }
}

// ---------------- kernel 3: softmax denominator (stores exp in-place) -------
__global__ void denom_kernel(const int* __restrict__ ei, int E) {
    int e = blockIdx.x * blockDim.x + threadIdx.x;
    if (e >= E) return;
    int dst = ei[E + e];
    float m = g_max[dst];
    if (!isfinite(m)) m = 0.0f;
    float ex = expf(g_att[e] - m);
    g_att[e] = ex;
    atomicAdd(&g_den[dst], ex);
}

// ---------------- kernel 3b: normalize attn ---------------------------------
__global__ void attn_kernel(const int* __restrict__ ei, int E) {
    int e = blockIdx.x * blockDim.x + threadIdx.x;
    if (e >= E) return;
    int dst = ei[E + e];
    g_att[e] = g_att[e] / (g_den[dst] + 1e-16f);
}

// ---------------- kernel 4: weighted scatter (vector red) -------------------
__global__ __launch_bounds__(256) void scatter_kernel(const int* __restrict__ ei, int E) {
    int idx = blockIdx.x * 256 + threadIdx.x;
    int e = idx >> 4;
    if (e >= E) return;
    int p = idx & 15;
    int dst = ei[E + e];
    float attn = g_att[e];
    float4 v = *(const float4*)(g_v + (size_t)e * 64 + p * 4);
    float* addr = g_aggr + (size_t)dst * 64 + p * 4;
    asm volatile("red.global.add.v4.f32 [%0], {%1, %2, %3, %4};"
                 :: "l"(addr), "f"(attn * v.x), "f"(attn * v.y),
                    "f"(attn * v.z), "f"(attn * v.w) : "memory");
}

// ---------------- kernel 5: epilogue -----------------------------------------
__global__ void final_kernel(const float* __restrict__ x, float* __restrict__ out, int N) {
    int i = blockIdx.x * blockDim.x + threadIdx.x;
    if (i < N * D) out[i] = x[i] + gelu_erf(g_aggr[i]);
}

// ---------------- launch ------------------------------------------------------
extern "C" void kernel_launch(void* const* d_in, const int* in_sizes, int n_in,
                              void* d_out, int out_size) {
    const float* x     = (const float*)d_in[0];
    const int*   ei    = (const int*)  d_in[1];
    const float* etime = (const float*)d_in[2];
    const float* esame = (const float*)d_in[4];
    const float* lng   = (const float*)d_in[5];
    const float* lnb   = (const float*)d_in[6];
    const float* Wt    = (const float*)d_in[7];
    const float* bt    = (const float*)d_in[8];
    const float* Wq    = (const float*)d_in[9];
    const float* bq    = (const float*)d_in[10];
    const float* Wks   = (const float*)d_in[11];
    const float* bks   = (const float*)d_in[12];
    const float* Wkd   = (const float*)d_in[13];
    const float* bkd   = (const float*)d_in[14];
    const float* Wvs   = (const float*)d_in[15];
    const float* bvs   = (const float*)d_in[16];
    const float* Wvd   = (const float*)d_in[17];
    const float* bvd   = (const float*)d_in[18];
    float* out = (float*)d_out;

    int N = in_sizes[0] / D;
    int E = in_sizes[2];
    if (N > MAXN) N = MAXN;
    if (E > MAXE) E = MAXE;

    float *pMsT, *pMdT, *pds, *pdd, *pus, *pud, *pec;
    cudaGetSymbolAddress((void**)&pMsT, g_MsT);
    cudaGetSymbolAddress((void**)&pMdT, g_MdT);
    cudaGetSymbolAddress((void**)&pds, g_ds);
    cudaGetSymbolAddress((void**)&pdd, g_dd);
    cudaGetSymbolAddress((void**)&pus, g_us);
    cudaGetSymbolAddress((void**)&pud, g_ud);
    cudaGetSymbolAddress((void**)&pec, g_ec);

    const int node_smem = NODE_SMEM_FLOATS * (int)sizeof(float);
    const int edge_smem = EDGE_SMEM_FLOATS * (int)sizeof(float);
    cudaFuncSetAttribute(node_kernel, cudaFuncAttributeMaxDynamicSharedMemorySize, node_smem);
    cudaFuncSetAttribute(edge_kernel, cudaFuncAttributeMaxDynamicSharedMemorySize, edge_smem);

    init_kernel<<<(N * D + 255) / 256, 256>>>(N);
    partition_kernel<<<(E + 255) / 256, 256>>>(esame, E);
    fold_kernel<<<1, 256>>>(Wq, bq, Wks, bks, pMsT, pds, pus, pec);
    fold_kernel<<<1, 256>>>(Wq, bq, Wkd, bkd, pMdT, pdd, pud, pec + 1);
    node_kernel<<<(N + 127) / 128, 256, node_smem>>>(x, lng, lnb, N);
    edge_kernel<<<(E + 127) / 128 + 1, 256, edge_smem>>>(ei, etime, Wt, bt,
                                                         Wvs, bvs, Wvd, bvd, E);
    denom_kernel<<<(E + 255) / 256, 256>>>(ei, E);
    attn_kernel<<<(E + 255) / 256, 256>>>(ei, E);
    scatter_kernel<<<(E * 16 + 255) / 256, 256>>>(ei, E);
    final_kernel<<<(N * D + 255) / 256, 256>>>(x, out, N);
}

// round 5
// speedup vs baseline: 3.0528x; 1.1467x over previous
#include <cuda_runtime.h>
#include <math.h>

#define MAXN 50000
#define MAXE 800000
#define D 64
#define XS 130             // XsT row stride (bank-conflict pad, 8B align)
#define WS 68              // weight smem row stride (bank pad, 16B align)
#define XSZ (65*XS + 2)    // pad so region after XsT is 16B-aligned

typedef unsigned long long ull;

// ---------------- scratch ---------------------------------------------------
__device__ float g_xn  [MAXN * D];
__device__ float g_qh_s[MAXN * D];
__device__ float g_qh_d[MAXN * D];
__device__ float g_c_s [MAXN];
__device__ float g_c_d [MAXN];
__device__ float g_den [MAXN];
__device__ float g_aggr[MAXN * D];
__device__ int   g_perm_s[MAXE];
__device__ int   g_perm_d[MAXE];
__device__ int   g_cnt[2];
// folded weights
__device__ float g_MsT[4096];   // [j][c] = sum_m Wks[m][c]*Wq[m][j]
__device__ float g_MdT[4096];
__device__ float g_ds[64], g_dd[64];   // Wk^T bq
__device__ float g_us[64], g_ud[64];   // bk^T Wq
__device__ float g_ec[2];              // bk . bq

__device__ __forceinline__ float gelu_erf(float x) {
    return 0.5f * x * (1.0f + erff(x * 0.70710678118654752440f));
}
__device__ __forceinline__ ull dup2(float x) {
    ull r; asm("mov.b64 %0, {%1, %1};" : "=l"(r) : "f"(x)); return r;
}
__device__ __forceinline__ void ffma2(ull& d, ull a, ull b) {
    asm("fma.rn.f32x2 %0, %1, %2, %0;" : "+l"(d) : "l"(a), "l"(b));
}
__device__ __forceinline__ float2 unpk(ull v) {
    float2 f; asm("mov.b64 {%0, %1}, %2;" : "=f"(f.x), "=f"(f.y) : "l"(v)); return f;
}

// ---------------- kernel 0: init --------------------------------------------
__global__ void init_kernel(int N) {
    int i = blockIdx.x * blockDim.x + threadIdx.x;
    if (i < N * D) g_aggr[i] = 0.0f;
    if (i < N) g_den[i] = 0.0f;
    if (i == 0) { g_cnt[0] = 0; g_cnt[1] = 0; }
}

// ---------------- kernel 0b: partition edges by edge_same -------------------
__global__ void partition_kernel(const float* __restrict__ esame, int E) {
    int e = blockIdx.x * blockDim.x + threadIdx.x;
    if (e >= E) return;
    if (esame[e] >= 0.5f) { int p = atomicAdd(&g_cnt[0], 1); g_perm_s[p] = e; }
    else                  { int p = atomicAdd(&g_cnt[1], 1); g_perm_d[p] = e; }
}

// ---------------- kernel 0c: fold Wq into Wk space (both in one launch) ------
__global__ __launch_bounds__(256) void fold_kernel(
    const float* __restrict__ Wq, const float* __restrict__ bq,
    const float* __restrict__ Wks, const float* __restrict__ bks,
    const float* __restrict__ Wkd, const float* __restrict__ bkd)
{
    int b = blockIdx.x;
    const float* Wk = b ? Wkd : Wks;
    const float* bk = b ? bkd : bks;
    float* MT   = b ? g_MdT : g_MsT;
    float* dvec = b ? g_dd : g_ds;
    float* uvec = b ? g_ud : g_us;

    __shared__ float sWq[4096], sWk[4096], sbq[64], sbk[64];
    int tid = threadIdx.x;
    for (int i = tid; i < 4096; i += 256) { sWq[i] = Wq[i]; sWk[i] = Wk[i]; }
    if (tid < 64) { sbq[tid] = bq[tid]; sbk[tid] = bk[tid]; }
    __syncthreads();
#pragma unroll
    for (int ii = 0; ii < 16; ii++) {
        int o = tid + ii * 256;
        int j = o >> 6, c = o & 63;
        float s = 0.0f;
#pragma unroll 8
        for (int m = 0; m < 64; m++) s += sWk[m * 64 + c] * sWq[m * 64 + j];
        MT[o] = s;
    }
    if (tid < 64) {
        float sd = 0.0f, su = 0.0f;
#pragma unroll 8
        for (int m = 0; m < 64; m++) {
            sd += sWk[m * 64 + tid] * sbq[m];
            su += sbk[m] * sWq[m * 64 + tid];
        }
        dvec[tid] = sd; uvec[tid] = su;
    }
    if (tid == 0) {
        float s = 0.0f;
        for (int m = 0; m < 64; m++) s += sbk[m] * sbq[m];
        g_ec[b] = s;
    }
}

// ---------------- kernel 1: layernorm + qh_s/qh_d/c --------------------------
#define NODE_SMEM_FLOATS (64*XS + 2*64*WS + 8*64)
__global__ __launch_bounds__(256, 2) void node_kernel(
    const float* __restrict__ x, const float* __restrict__ gamma,
    const float* __restrict__ beta, int N)
{
    extern __shared__ float ns[];
    float* XsT = ns;                    // [64][XS]
    float* sMs = XsT + 64 * XS;
    float* sMd = sMs + 64 * WS;
    float* sg  = sMd + 64 * WS;
    float* sb  = sg + 64;
    float* sus = sb + 64;
    float* sud = sus + 64;
    float* sds = sud + 64;
    float* sdd = sds + 64;

    int tid = threadIdx.x;
    for (int i = tid; i < 4096; i += 256) {
        int j = i >> 6, c = i & 63;
        sMs[j * WS + c] = g_MsT[i];
        sMd[j * WS + c] = g_MdT[i];
    }
    if (tid < 64) {
        sg[tid] = gamma[tid]; sb[tid] = beta[tid];
        sus[tid] = g_us[tid]; sud[tid] = g_ud[tid];
        sds[tid] = g_ds[tid]; sdd[tid] = g_dd[tid];
    }
    __syncthreads();

    int n0 = blockIdx.x * 128;
    int cnt = min(128, N - n0);

    // ---- LN gather: 2 threads per node ----
    {
        int nl = tid >> 1, half = tid & 1;
        bool act = nl < cnt;
        int n = n0 + nl;
        float4 xv[8];
        float s = 0.0f, t = 0.0f;
        if (act) {
            const float4* xr = (const float4*)(x + (size_t)n * 64) + half * 8;
#pragma unroll
            for (int kk = 0; kk < 8; kk++) {
                xv[kk] = xr[kk];
                s += xv[kk].x + xv[kk].y + xv[kk].z + xv[kk].w;
                t += xv[kk].x * xv[kk].x + xv[kk].y * xv[kk].y
                   + xv[kk].z * xv[kk].z + xv[kk].w * xv[kk].w;
            }
        }
        s += __shfl_xor_sync(0xffffffffu, s, 1);
        t += __shfl_xor_sync(0xffffffffu, t, 1);
        float mu = s * (1.0f / 64.0f);
        float var = t * (1.0f / 64.0f) - mu * mu;
        float inv = rsqrtf(var + 1e-5f);
        float cs = 0.0f, cd = 0.0f;
        if (act) {
            float* gx = g_xn + (size_t)n * 64 + half * 32;
#pragma unroll
            for (int kk = 0; kk < 8; kk++) {
                int c0 = half * 32 + 4 * kk;
                float v[4] = {xv[kk].x, xv[kk].y, xv[kk].z, xv[kk].w};
                float xn4[4];
#pragma unroll
                for (int p = 0; p < 4; p++) {
                    int c = c0 + p;
                    float xn = (v[p] - mu) * inv * sg[c] + sb[c];
                    xn4[p] = xn;
                    XsT[c * XS + nl] = xn;
                    cs += xn * sus[c];
                    cd += xn * sud[c];
                }
                *(float4*)(gx + 4 * kk) = make_float4(xn4[0], xn4[1], xn4[2], xn4[3]);
            }
        }
        cs += __shfl_xor_sync(0xffffffffu, cs, 1);
        cd += __shfl_xor_sync(0xffffffffu, cd, 1);
        if (act && half == 0) {
            g_c_s[n] = cs + g_ec[0];
            g_c_d[n] = cd + g_ec[1];
        }
    }
    __syncthreads();

    // ---- two GEMMs: qh = XsT^T @ M + d ----
    int ty = tid >> 3, tx = tid & 7;
    int row0 = ty << 2, col0 = tx << 3;
#pragma unroll
    for (int pass = 0; pass < 2; pass++) {
        const float* M = pass ? sMd : sMs;
        const float* dv = pass ? sdd : sds;
        float* outp = pass ? g_qh_d : g_qh_s;
        ull acc[16];
        {
            const ull* dp = (const ull*)(dv + col0);
            ull w0 = dp[0], w1 = dp[1], w2 = dp[2], w3 = dp[3];
#pragma unroll
            for (int i = 0; i < 4; i++) {
                acc[i * 4] = w0; acc[i * 4 + 1] = w1; acc[i * 4 + 2] = w2; acc[i * 4 + 3] = w3;
            }
        }
#pragma unroll 4
        for (int k = 0; k < 64; k++) {
            const ull* axp = (const ull*)(XsT + k * XS + row0);
            float2 f01 = unpk(axp[0]), f23 = unpk(axp[1]);
            float aa[4] = {f01.x, f01.y, f23.x, f23.y};
            const ull* bp = (const ull*)(M + k * WS + col0);
            ull w0 = bp[0], w1 = bp[1], w2 = bp[2], w3 = bp[3];
#pragma unroll
            for (int i = 0; i < 4; i++) {
                ull ad = dup2(aa[i]);
                ffma2(acc[i * 4],     ad, w0);
                ffma2(acc[i * 4 + 1], ad, w1);
                ffma2(acc[i * 4 + 2], ad, w2);
                ffma2(acc[i * 4 + 3], ad, w3);
            }
        }
#pragma unroll
        for (int i = 0; i < 4; i++) {
            int nl = row0 + i;
            if (nl < cnt) {
                float* dp = outp + (size_t)(n0 + nl) * 64 + col0;
                float2 v0 = unpk(acc[i * 4]),     v1 = unpk(acc[i * 4 + 1]);
                float2 v2 = unpk(acc[i * 4 + 2]), v3 = unpk(acc[i * 4 + 3]);
                *(float4*)dp       = make_float4(v0.x, v0.y, v1.x, v1.y);
                *(float4*)(dp + 4) = make_float4(v2.x, v2.y, v3.x, v3.y);
            }
        }
    }
}

// ---------------- kernel 2: fused edge GEMM + softmax-scatter ----------------
#define EDGE_SMEM_FLOATS (XSZ + 65*WS + 128 + 128 + 64 + 64 + 64 + 128)

__global__ __launch_bounds__(256, 2) void edge_kernel(
    const int* __restrict__ ei, const float* __restrict__ etime,
    const float* __restrict__ Wt,  const float* __restrict__ bt,
    const float* __restrict__ Wvs, const float* __restrict__ bvs,
    const float* __restrict__ Wvd, const float* __restrict__ bvd,
    int E)
{
    extern __shared__ float sm[];
    float* XsT  = sm;                  // [65][XS], reused as xtT
    float* Ws   = XsT + XSZ;           // [65][WS]: W1 then W2
    float* st   = Ws + 65 * WS;        // [128] times
    float* sex  = st + 128;            // [128] exp(att)
    float* sdiv = sex + 128;           // [64]
    float* sbt  = sdiv + 64;           // [64]
    float* sbv  = sbt + 64;            // [64]
    int* sdst   = (int*)(sbv + 64);    // [128]

    int tid = threadIdx.x;
    int bid = blockIdx.x;

    int cs = g_cnt[0];
    int ts = (cs + 127) >> 7;
    const int* list; int off, cnt, same;
    if (bid < ts) {
        list = g_perm_s; off = bid << 7; cnt = min(128, cs - off); same = 1;
    } else {
        int cd = g_cnt[1];
        off = (bid - ts) << 7;
        if (off >= cd) return;
        list = g_perm_d; cnt = min(128, cd - off); same = 0;
    }
    const float* Wv = same ? Wvs : Wvd;
    const float* bv = same ? bvs : bvd;
    const float* qh = same ? g_qh_s : g_qh_d;
    const float* cv = same ? g_c_s  : g_c_d;

    // ---- prologue: W1 (transposed), biases, gather X (2 thr/edge) ----
    for (int i = tid; i < 65 * 64; i += 256) {
        int m = i / 65, k = i % 65;
        Ws[k * WS + m] = Wt[i];
    }
    if (tid < 64) {
        sbt[tid] = bt[tid];
        sbv[tid] = bv[tid];
        sdiv[tid] = powf(10000.0f, -(float)(2 * (tid >> 1)) / 64.0f);
    }
    {
        int el = tid >> 1, half = tid & 1;
        bool act = el < cnt;
        int pe = 0, src = 0, dstn = 0; float tt = 0.0f;
        if (act) { pe = list[off + el]; src = ei[pe]; dstn = ei[E + pe]; tt = etime[pe]; }
        if (half == 0) {
            sdst[el] = dstn; st[el] = tt;
            XsT[64 * XS + el] = tt;
        }
        const float4* xr = (const float4*)(g_xn + (size_t)src * 64) + half * 8;
#pragma unroll
        for (int kk = 0; kk < 8; kk++) {
            float4 v = act ? xr[kk] : make_float4(0.f, 0.f, 0.f, 0.f);
            int c0 = half * 32 + 4 * kk;
            XsT[(c0 + 0) * XS + el] = v.x;
            XsT[(c0 + 1) * XS + el] = v.y;
            XsT[(c0 + 2) * XS + el] = v.z;
            XsT[(c0 + 3) * XS + el] = v.w;
        }
    }
    __syncthreads();

    int ty = tid >> 3, tx = tid & 7;
    int row0 = ty << 2, col0 = tx << 3;

    // ---- GEMM1: xt_pre = X(128x65) @ W1(65x64) ----
    ull acc[16];
#pragma unroll
    for (int j = 0; j < 8; j++) {
        ull bd = dup2(sbt[col0 + j]);
        acc[j] = bd; acc[8 + j] = bd;
    }
#pragma unroll 5
    for (int k = 0; k < 65; k++) {
        const ull* ap = (const ull*)(XsT + k * XS + row0);
        ull a0 = ap[0], a1 = ap[1];
        const float* bp = Ws + k * WS + col0;
        float4 b0 = *(const float4*)bp, b1 = *(const float4*)(bp + 4);
        float bb[8] = {b0.x, b0.y, b0.z, b0.w, b1.x, b1.y, b1.z, b1.w};
#pragma unroll
        for (int j = 0; j < 8; j++) {
            ull bd = dup2(bb[j]);
            ffma2(acc[j],     a0, bd);
            ffma2(acc[8 + j], a1, bd);
        }
    }
    __syncthreads();   // done reading XsT / Ws

    // ---- start W2 load into registers (coalesced) ----
    float w2r[16];
#pragma unroll
    for (int ii = 0; ii < 16; ii++) w2r[ii] = Wv[tid + ii * 256];

    // ---- epilogue1: gelu + temporal enc; att partials; store xtT ----
    float* xtT = XsT;
    float pa[4] = {0, 0, 0, 0};
#pragma unroll
    for (int i2 = 0; i2 < 2; i2++) {
        int e0 = row0 + 2 * i2, e1 = e0 + 1;
        float t0 = st[e0] * 200.0f, t1 = st[e1] * 200.0f;
        const float4* q0p = (const float4*)(qh + (size_t)sdst[e0] * 64 + col0);
        const float4* q1p = (const float4*)(qh + (size_t)sdst[e1] * 64 + col0);
        float4 qa = q0p[0], qb = q0p[1], qc = q1p[0], qd = q1p[1];
        float qv0[8] = {qa.x, qa.y, qa.z, qa.w, qb.x, qb.y, qb.z, qb.w};
        float qv1[8] = {qc.x, qc.y, qc.z, qc.w, qd.x, qd.y, qd.z, qd.w};
#pragma unroll
        for (int j2 = 0; j2 < 4; j2++) {
            float dv = sdiv[col0 + 2 * j2];
            float s0, c0, s1, c1;
            sincosf(t0 * dv, &s0, &c0);
            sincosf(t1 * dv, &s1, &c1);
            float2 ue = unpk(acc[i2 * 8 + 2 * j2]);
            float2 uo = unpk(acc[i2 * 8 + 2 * j2 + 1]);
            float x00 = gelu_erf(ue.x) + s0;
            float x10 = gelu_erf(ue.y) + s1;
            float x01 = gelu_erf(uo.x) + c0;
            float x11 = gelu_erf(uo.y) + c1;
            pa[2 * i2]     += x00 * qv0[2 * j2] + x01 * qv0[2 * j2 + 1];
            pa[2 * i2 + 1] += x10 * qv1[2 * j2] + x11 * qv1[2 * j2 + 1];
            *(float2*)(xtT + (col0 + 2 * j2) * XS + e0)     = make_float2(x00, x10);
            *(float2*)(xtT + (col0 + 2 * j2 + 1) * XS + e0) = make_float2(x01, x11);
        }
    }
    // att: shuffle-reduce over the 8 tx lanes; then exp + den atomic
#pragma unroll
    for (int o = 4; o; o >>= 1) {
#pragma unroll
        for (int i = 0; i < 4; i++) pa[i] += __shfl_xor_sync(0xffffffffu, pa[i], o);
    }
    if (tx < 4) {
        int e = row0 + tx;
        if (e < cnt) {
            int dn = sdst[e];
            float att = (pa[tx] + cv[dn]) * 0.125f;
            float ex = expf(att);          // softmax shift-invariant; att is O(1)
            sex[e] = ex;
            atomicAdd(&g_den[dn], ex);
        }
    }
    // ---- store W2 (transposed) ----
#pragma unroll
    for (int ii = 0; ii < 16; ii++) {
        int i = tid + ii * 256;
        int m = i >> 6, k = i & 63;
        Ws[k * WS + m] = w2r[ii];
    }
    __syncthreads();

    // ---- GEMM2: v = xt(128x64) @ W2(64x64); scatter ex*v directly ----
    ull acc2[16];
    {
        const ull* bvp = (const ull*)(sbv + col0);
        ull w0 = bvp[0], w1 = bvp[1], w2 = bvp[2], w3 = bvp[3];
#pragma unroll
        for (int i = 0; i < 4; i++) {
            acc2[i * 4] = w0; acc2[i * 4 + 1] = w1; acc2[i * 4 + 2] = w2; acc2[i * 4 + 3] = w3;
        }
    }
#pragma unroll 4
    for (int k = 0; k < 64; k++) {
        const ull* axp = (const ull*)(xtT + k * XS + row0);
        float2 f01 = unpk(axp[0]), f23 = unpk(axp[1]);
        float aa[4] = {f01.x, f01.y, f23.x, f23.y};
        const ull* bp = (const ull*)(Ws + k * WS + col0);
        ull w0 = bp[0], w1 = bp[1], w2 = bp[2], w3 = bp[3];
#pragma unroll
        for (int i = 0; i < 4; i++) {
            ull ad = dup2(aa[i]);
            ffma2(acc2[i * 4],     ad, w0);
            ffma2(acc2[i * 4 + 1], ad, w1);
            ffma2(acc2[i * 4 + 2], ad, w2);
            ffma2(acc2[i * 4 + 3], ad, w3);
        }
    }
#pragma unroll
    for (int i = 0; i < 4; i++) {
        int e = row0 + i;
        if (e < cnt) {
            float ex = sex[e];
            float* dp = g_aggr + (size_t)sdst[e] * 64 + col0;
            float2 v0 = unpk(acc2[i * 4]),     v1 = unpk(acc2[i * 4 + 1]);
            float2 v2 = unpk(acc2[i * 4 + 2]), v3 = unpk(acc2[i * 4 + 3]);
            asm volatile("red.global.add.v4.f32 [%0], {%1, %2, %3, %4};"
                         :: "l"(dp), "f"(ex * v0.x), "f"(ex * v0.y),
                            "f"(ex * v1.x), "f"(ex * v1.y) : "memory");
            asm volatile("red.global.add.v4.f32 [%0], {%1, %2, %3, %4};"
                         :: "l"(dp + 4), "f"(ex * v2.x), "f"(ex * v2.y),
                            "f"(ex * v3.x), "f"(ex * v3.y) : "memory");
        }
    }
}

// ---------------- kernel 5: epilogue (normalize by den) ----------------------
__global__ void final_kernel(const float* __restrict__ x, float* __restrict__ out, int N) {
    int i = blockIdx.x * blockDim.x + threadIdx.x;
    if (i < N * D) {
        float den = g_den[i >> 6];
        out[i] = x[i] + gelu_erf(g_aggr[i] / (den + 1e-16f));
    }
}

// ---------------- launch ------------------------------------------------------
extern "C" void kernel_launch(void* const* d_in, const int* in_sizes, int n_in,
                              void* d_out, int out_size) {
    const float* x     = (const float*)d_in[0];
    const int*   ei    = (const int*)  d_in[1];
    const float* etime = (const float*)d_in[2];
    const float* esame = (const float*)d_in[4];
    const float* lng   = (const float*)d_in[5];
    const float* lnb   = (const float*)d_in[6];
    const float* Wt    = (const float*)d_in[7];
    const float* bt    = (const float*)d_in[8];
    const float* Wq    = (const float*)d_in[9];
    const float* bq    = (const float*)d_in[10];
    const float* Wks   = (const float*)d_in[11];
    const float* bks   = (const float*)d_in[12];
    const float* Wkd   = (const float*)d_in[13];
    const float* bkd   = (const float*)d_in[14];
    const float* Wvs   = (const float*)d_in[15];
    const float* bvs   = (const float*)d_in[16];
    const float* Wvd   = (const float*)d_in[17];
    const float* bvd   = (const float*)d_in[18];
    float* out = (float*)d_out;

    int N = in_sizes[0] / D;
    int E = in_sizes[2];
    if (N > MAXN) N = MAXN;
    if (E > MAXE) E = MAXE;

    const int node_smem = NODE_SMEM_FLOATS * (int)sizeof(float);
    const int edge_smem = EDGE_SMEM_FLOATS * (int)sizeof(float);
    cudaFuncSetAttribute(node_kernel, cudaFuncAttributeMaxDynamicSharedMemorySize, node_smem);
    cudaFuncSetAttribute(edge_kernel, cudaFuncAttributeMaxDynamicSharedMemorySize, edge_smem);

    init_kernel<<<(N * D + 255) / 256, 256>>>(N);
    partition_kernel<<<(E + 255) / 256, 256>>>(esame, E);
    fold_kernel<<<2, 256>>>(Wq, bq, Wks, bks, Wkd, bkd);
    node_kernel<<<(N + 127) / 128, 256, node_smem>>>(x, lng, lnb, N);
    edge_kernel<<<(E + 127) / 128 + 1, 256, edge_smem>>>(ei, etime, Wt, bt,
                                                         Wvs, bvs, Wvd, bvd, E);
    final_kernel<<<(N * D + 255) / 256, 256>>>(x, out, N);
}

// round 8
// speedup vs baseline: 4.7273x; 1.5485x over previous
#include <cuda_runtime.h>
#include <cuda_bf16.h>
#include <math.h>
#include <stdint.h>

#define MAXN 50000
#define MAXE 800000
#define D 64
#define XS 130
#define WS 68

// tcgen05 is arch-SPECIFIC: only emit it in the sm_103a/'a'-target device pass.
#if !defined(__CUDA_ARCH__) || defined(__CUDA_ARCH_FEAT_SM103_ALL) || \
    defined(__CUDA_ARCH_FEAT_SM100_ALL) || defined(__CUDA_ARCH_SPECIFIC__) || \
    defined(__CUDA_ARCH_FAMILY_SPECIFIC__)
#define TC_OK 1
#else
#define TC_OK 0
#endif

typedef unsigned long long ull;

// ---------------- scratch ---------------------------------------------------
__device__ float g_xn  [MAXN * D];
__device__ float g_qh_s[MAXN * D];
__device__ float g_qh_d[MAXN * D];
__device__ float g_c_s [MAXN];
__device__ float g_c_d [MAXN];
__device__ float g_den [MAXN];
__device__ float g_aggr[MAXN * D];
__device__ int   g_perm_s[MAXE];
__device__ int   g_perm_d[MAXE];
__device__ int   g_cnt[2];
__device__ float g_MsT[4096];
__device__ float g_MdT[4096];
__device__ float g_ds[64], g_dd[64];
__device__ float g_us[64], g_ud[64];
__device__ float g_ec[2];

__device__ __forceinline__ float gelu_erf(float x) {
    return 0.5f * x * (1.0f + erff(x * 0.70710678118654752440f));
}
__device__ __forceinline__ ull dup2(float x) {
    ull r; asm("mov.b64 %0, {%1, %1};" : "=l"(r) : "f"(x)); return r;
}
__device__ __forceinline__ void ffma2(ull& d, ull a, ull b) {
    asm("fma.rn.f32x2 %0, %1, %2, %0;" : "+l"(d) : "l"(a), "l"(b));
}
__device__ __forceinline__ float2 unpk(ull v) {
    float2 f; asm("mov.b64 {%0, %1}, %2;" : "=f"(f.x), "=f"(f.y) : "l"(v)); return f;
}

// ---------------- bf16 pack helpers ------------------------------------------
__device__ __forceinline__ uint32_t packbf(float x0, float x1) {
    uint32_t r;
    asm("cvt.rn.bf16x2.f32 %0, %2, %1;" : "=r"(r) : "f"(x0), "f"(x1));
    return r;
}
__device__ __forceinline__ void split2(float x0, float x1, uint32_t& hp, uint32_t& lp) {
    hp = packbf(x0, x1);
    float h0 = __uint_as_float(hp << 16);
    float h1 = __uint_as_float(hp & 0xffff0000u);
    lp = packbf(x0 - h0, x1 - h1);
}

__device__ __forceinline__ uint32_t smem_u32(const void* p) {
    uint32_t a;
    asm("{ .reg .u64 t; cvta.to.shared.u64 t, %1; cvt.u32.u64 %0, t; }"
        : "=r"(a) : "l"(p));
    return a;
}
#define SW128(o) ((o) ^ (((o) >> 3) & 0x70))

__device__ __forceinline__ uint64_t mkdesc(uint32_t addr) {
    const uint64_t base = (2ull << 61) | (1ull << 46) | (64ull << 32) | (1ull << 16);
    return base | ((addr >> 4) & 0x3FFF);
}

// idesc kind::f16, bf16 x bf16 -> f32, M=128, N=64
#define MMA_IDESC 0x08100490u

#if TC_OK
__device__ __forceinline__ void mma_f16_ss(uint32_t d_tmem, uint64_t a_desc,
                                           uint64_t b_desc, uint32_t en) {
    asm volatile(
        "{\n\t"
        ".reg .pred p;\n\t"
        "setp.ne.u32 p, %5, 0;\n\t"
        "tcgen05.mma.cta_group::1.kind::f16 [%0], %1, %2, %3, {%4, %4, %4, %4}, p;\n\t"
        "}"
        :: "r"(d_tmem), "l"(a_desc), "l"(b_desc), "r"(MMA_IDESC), "r"(0u), "r"(en)
        : "memory");
}

#define TC_ALLOC(smem_addr, n) \
    asm volatile("tcgen05.alloc.cta_group::1.sync.aligned.shared::cta.b32 [%0], %1;" \
                 :: "r"(smem_addr), "r"((uint32_t)(n)) : "memory")
#define TC_RELINQ() \
    asm volatile("tcgen05.relinquish_alloc_permit.cta_group::1.sync.aligned;")
#define TC_DEALLOC(tmem, n) \
    asm volatile("tcgen05.dealloc.cta_group::1.sync.aligned.b32 %0, %1;" \
                 :: "r"(tmem), "r"((uint32_t)(n)))
#define TC_COMMIT(mbar) \
    asm volatile("tcgen05.commit.cta_group::1.mbarrier::arrive::one.shared::cluster.b64 [%0];" \
                 :: "r"(mbar) : "memory")
#define TC_FENCE_AFTER() \
    asm volatile("tcgen05.fence::after_thread_sync;" ::: "memory")
#define TC_WAIT_LD() \
    asm volatile("tcgen05.wait::ld.sync.aligned;" ::: "memory")
#define FENCE_PROXY() \
    asm volatile("fence.proxy.async.shared::cta;" ::: "memory")
#define MBAR_INIT(mbar, n) \
    asm volatile("mbarrier.init.shared.b64 [%0], %1;" :: "r"(mbar), "r"((uint32_t)(n)) : "memory")
#define MBAR_INVAL(mbar) \
    asm volatile("mbarrier.inval.shared.b64 [%0];" :: "r"(mbar) : "memory")

__device__ __forceinline__ void mbar_wait(uint32_t mbar, uint32_t parity) {
    asm volatile(
        "{\n\t"
        ".reg .pred P;\n\t"
        "WLOOP%=:\n\t"
        "mbarrier.try_wait.parity.acquire.cta.shared::cta.b64 P, [%0], %1, 0x989680;\n\t"
        "@P bra.uni WDONE%=;\n\t"
        "bra.uni WLOOP%=;\n\t"
        "WDONE%=:\n\t"
        "}"
        :: "r"(mbar), "r"(parity) : "memory");
}

#define TC_LD_X32(r, tmem_addr) \
    asm volatile( \
        "tcgen05.ld.sync.aligned.32x32b.x32.b32 " \
        "{%0, %1, %2, %3, %4, %5, %6, %7, " \
        " %8, %9, %10, %11, %12, %13, %14, %15, " \
        " %16, %17, %18, %19, %20, %21, %22, %23, " \
        " %24, %25, %26, %27, %28, %29, %30, %31}, [%32];" \
        : "=r"((r)[0]),  "=r"((r)[1]),  "=r"((r)[2]),  "=r"((r)[3]), \
          "=r"((r)[4]),  "=r"((r)[5]),  "=r"((r)[6]),  "=r"((r)[7]), \
          "=r"((r)[8]),  "=r"((r)[9]),  "=r"((r)[10]), "=r"((r)[11]), \
          "=r"((r)[12]), "=r"((r)[13]), "=r"((r)[14]), "=r"((r)[15]), \
          "=r"((r)[16]), "=r"((r)[17]), "=r"((r)[18]), "=r"((r)[19]), \
          "=r"((r)[20]), "=r"((r)[21]), "=r"((r)[22]), "=r"((r)[23]), \
          "=r"((r)[24]), "=r"((r)[25]), "=r"((r)[26]), "=r"((r)[27]), \
          "=r"((r)[28]), "=r"((r)[29]), "=r"((r)[30]), "=r"((r)[31]) \
        : "r"(tmem_addr))
#endif  // TC_OK

// ---------------- kernel 0: init --------------------------------------------
__global__ void init_kernel(int N) {
    int i = blockIdx.x * blockDim.x + threadIdx.x;
    if (i < N * D) g_aggr[i] = 0.0f;
    if (i < N) g_den[i] = 0.0f;
    if (i == 0) { g_cnt[0] = 0; g_cnt[1] = 0; }
}

// ---------------- kernel 0b: partition edges ---------------------------------
__global__ void partition_kernel(const float* __restrict__ esame, int E) {
    int e = blockIdx.x * blockDim.x + threadIdx.x;
    if (e >= E) return;
    if (esame[e] >= 0.5f) { int p = atomicAdd(&g_cnt[0], 1); g_perm_s[p] = e; }
    else                  { int p = atomicAdd(&g_cnt[1], 1); g_perm_d[p] = e; }
}

// ---------------- kernel 0c: fold Wq into Wk space ---------------------------
__global__ __launch_bounds__(256) void fold_kernel(
    const float* __restrict__ Wq, const float* __restrict__ bq,
    const float* __restrict__ Wks, const float* __restrict__ bks,
    const float* __restrict__ Wkd, const float* __restrict__ bkd)
{
    int b = blockIdx.x;
    const float* Wk = b ? Wkd : Wks;
    const float* bk = b ? bkd : bks;
    float* MT   = b ? g_MdT : g_MsT;
    float* dvec = b ? g_dd : g_ds;
    float* uvec = b ? g_ud : g_us;

    __shared__ float sWq[4096], sWk[4096], sbq[64], sbk[64];
    int tid = threadIdx.x;
    for (int i = tid; i < 4096; i += 256) { sWq[i] = Wq[i]; sWk[i] = Wk[i]; }
    if (tid < 64) { sbq[tid] = bq[tid]; sbk[tid] = bk[tid]; }
    __syncthreads();
#pragma unroll
    for (int ii = 0; ii < 16; ii++) {
        int o = tid + ii * 256;
        int j = o >> 6, c = o & 63;
        float s = 0.0f;
#pragma unroll 8
        for (int m = 0; m < 64; m++) s += sWk[m * 64 + c] * sWq[m * 64 + j];
        MT[o] = s;
    }
    if (tid < 64) {
        float sd = 0.0f, su = 0.0f;
#pragma unroll 8
        for (int m = 0; m < 64; m++) {
            sd += sWk[m * 64 + tid] * sbq[m];
            su += sbk[m] * sWq[m * 64 + tid];
        }
        dvec[tid] = sd; uvec[tid] = su;
    }
    if (tid == 0) {
        float s = 0.0f;
        for (int m = 0; m < 64; m++) s += sbk[m] * sbq[m];
        g_ec[b] = s;
    }
}

// ---------------- kernel 1: layernorm + qh_s/qh_d/c --------------------------
#define NODE_SMEM_FLOATS (64*XS + 2*64*WS + 8*64)
__global__ __launch_bounds__(256, 2) void node_kernel(
    const float* __restrict__ x, const float* __restrict__ gamma,
    const float* __restrict__ beta, int N)
{
    extern __shared__ float ns[];
    float* XsT = ns;
    float* sMs = XsT + 64 * XS;
    float* sMd = sMs + 64 * WS;
    float* sg  = sMd + 64 * WS;
    float* sb  = sg + 64;
    float* sus = sb + 64;
    float* sud = sus + 64;
    float* sds = sud + 64;
    float* sdd = sds + 64;

    int tid = threadIdx.x;
    for (int i = tid; i < 4096; i += 256) {
        int j = i >> 6, c = i & 63;
        sMs[j * WS + c] = g_MsT[i];
        sMd[j * WS + c] = g_MdT[i];
    }
    if (tid < 64) {
        sg[tid] = gamma[tid]; sb[tid] = beta[tid];
        sus[tid] = g_us[tid]; sud[tid] = g_ud[tid];
        sds[tid] = g_ds[tid]; sdd[tid] = g_dd[tid];
    }
    __syncthreads();

    int n0 = blockIdx.x * 128;
    int cnt = min(128, N - n0);

    {
        int nl = tid >> 1, half = tid & 1;
        bool act = nl < cnt;
        int n = n0 + nl;
        float4 xv[8];
        float s = 0.0f, t = 0.0f;
        if (act) {
            const float4* xr = (const float4*)(x + (size_t)n * 64) + half * 8;
#pragma unroll
            for (int kk = 0; kk < 8; kk++) {
                xv[kk] = xr[kk];
                s += xv[kk].x + xv[kk].y + xv[kk].z + xv[kk].w;
                t += xv[kk].x * xv[kk].x + xv[kk].y * xv[kk].y
                   + xv[kk].z * xv[kk].z + xv[kk].w * xv[kk].w;
            }
        }
        s += __shfl_xor_sync(0xffffffffu, s, 1);
        t += __shfl_xor_sync(0xffffffffu, t, 1);
        float mu = s * (1.0f / 64.0f);
        float var = t * (1.0f / 64.0f) - mu * mu;
        float inv = rsqrtf(var + 1e-5f);
        float cs = 0.0f, cd = 0.0f;
        if (act) {
            float* gx = g_xn + (size_t)n * 64 + half * 32;
#pragma unroll
            for (int kk = 0; kk < 8; kk++) {
                int c0 = half * 32 + 4 * kk;
                float v[4] = {xv[kk].x, xv[kk].y, xv[kk].z, xv[kk].w};
                float xn4[4];
#pragma unroll
                for (int p = 0; p < 4; p++) {
                    int c = c0 + p;
                    float xn = (v[p] - mu) * inv * sg[c] + sb[c];
                    xn4[p] = xn;
                    XsT[c * XS + nl] = xn;
                    cs += xn * sus[c];
                    cd += xn * sud[c];
                }
                *(float4*)(gx + 4 * kk) = make_float4(xn4[0], xn4[1], xn4[2], xn4[3]);
            }
        }
        cs += __shfl_xor_sync(0xffffffffu, cs, 1);
        cd += __shfl_xor_sync(0xffffffffu, cd, 1);
        if (act && half == 0) {
            g_c_s[n] = cs + g_ec[0];
            g_c_d[n] = cd + g_ec[1];
        }
    }
    __syncthreads();

    int ty = tid >> 3, tx = tid & 7;
    int row0 = ty << 2, col0 = tx << 3;
#pragma unroll
    for (int pass = 0; pass < 2; pass++) {
        const float* M = pass ? sMd : sMs;
        const float* dv = pass ? sdd : sds;
        float* outp = pass ? g_qh_d : g_qh_s;
        ull acc[16];
        {
            const ull* dp = (const ull*)(dv + col0);
            ull w0 = dp[0], w1 = dp[1], w2 = dp[2], w3 = dp[3];
#pragma unroll
            for (int i = 0; i < 4; i++) {
                acc[i * 4] = w0; acc[i * 4 + 1] = w1; acc[i * 4 + 2] = w2; acc[i * 4 + 3] = w3;
            }
        }
#pragma unroll 4
        for (int k = 0; k < 64; k++) {
            const ull* axp = (const ull*)(XsT + k * XS + row0);
            float2 f01 = unpk(axp[0]), f23 = unpk(axp[1]);
            float aa[4] = {f01.x, f01.y, f23.x, f23.y};
            const ull* bp = (const ull*)(M + k * WS + col0);
            ull w0 = bp[0], w1 = bp[1], w2 = bp[2], w3 = bp[3];
#pragma unroll
            for (int i = 0; i < 4; i++) {
                ull ad = dup2(aa[i]);
                ffma2(acc[i * 4],     ad, w0);
                ffma2(acc[i * 4 + 1], ad, w1);
                ffma2(acc[i * 4 + 2], ad, w2);
                ffma2(acc[i * 4 + 3], ad, w3);
            }
        }
#pragma unroll
        for (int i = 0; i < 4; i++) {
            int nl = row0 + i;
            if (nl < cnt) {
                float* dp = outp + (size_t)(n0 + nl) * 64 + col0;
                float2 v0 = unpk(acc[i * 4]),     v1 = unpk(acc[i * 4 + 1]);
                float2 v2 = unpk(acc[i * 4 + 2]), v3 = unpk(acc[i * 4 + 3]);
                *(float4*)dp       = make_float4(v0.x, v0.y, v1.x, v1.y);
                *(float4*)(dp + 4) = make_float4(v2.x, v2.y, v3.x, v3.y);
            }
        }
    }
}

// ---------------- kernel 2: tensor-core edge kernel --------------------------
#define OFF_AHI 0
#define OFF_ALO 16384
#define OFF_W1H 32768
#define OFF_W1L 40960
#define OFF_W2H 49152
#define OFF_W2L 57344
#define OFF_SBT 65536
#define OFF_SBV 65792
#define OFF_WTL 66048
#define OFF_SDV 66304
#define OFF_TMP 66560
#define OFF_MBR 66568
#define EDGE_SMEM_BYTES (1024 + 66576 + 48)

__global__ __launch_bounds__(128)
void edge_tc_kernel(
    const int* __restrict__ ei, const float* __restrict__ etime,
    const float* __restrict__ Wt,
    const float* __restrict__ bt,
    const float* __restrict__ Wvs, const float* __restrict__ bvs,
    const float* __restrict__ Wvd, const float* __restrict__ bvd,
    int E)
{
    int tid = threadIdx.x;
    int bid = blockIdx.x;

    // tile select
    int cs = g_cnt[0];
    int ts = (cs + 127) >> 7;
    const int* list; int off, cnt, same;
    if (bid < ts) {
        list = g_perm_s; off = bid << 7; cnt = min(128, cs - off); same = 1;
    } else {
        int cd = g_cnt[1];
        off = (bid - ts) << 7;
        if (off >= cd) return;
        list = g_perm_d; cnt = min(128, cd - off); same = 0;
    }
    const float* Wv = same ? Wvs : Wvd;
    const float* bv = same ? bvs : bvd;
    const float* qh = same ? g_qh_s : g_qh_d;
    const float* cv = same ? g_c_s  : g_c_d;

#if TC_OK
    extern __shared__ char dsm_raw[];
    uint32_t raw_u = smem_u32(dsm_raw);
    uint32_t base_u = (raw_u + 1023u) & ~1023u;
    char* sb = dsm_raw + (base_u - raw_u);
    int wid = tid >> 5;

    if (wid == 0) {
        TC_ALLOC(base_u + OFF_TMP, 128);
        TC_RELINQ();
    }
    if (tid == 0) MBAR_INIT(base_u + OFF_MBR, 1);

    float* sbt  = (float*)(sb + OFF_SBT);
    float* sbv  = (float*)(sb + OFF_SBV);
    float* wtl  = (float*)(sb + OFF_WTL);
    float* sdiv = (float*)(sb + OFF_SDV);

    // ---- weights -> bf16 hi/lo, SW128 swizzled ----
    for (int i = tid; i < 2048; i += 128) {
        int m = i >> 5, k2 = (i & 31) * 2;
        uint32_t byte = (uint32_t)(m * 128 + k2 * 2);
        uint32_t swo = SW128(byte);
        uint32_t hp, lp;
        split2(Wt[m * 65 + k2], Wt[m * 65 + k2 + 1], hp, lp);
        *(uint32_t*)(sb + OFF_W1H + swo) = hp;
        *(uint32_t*)(sb + OFF_W1L + swo) = lp;
        split2(Wv[m * 64 + k2], Wv[m * 64 + k2 + 1], hp, lp);
        *(uint32_t*)(sb + OFF_W2H + swo) = hp;
        *(uint32_t*)(sb + OFF_W2L + swo) = lp;
    }
    if (tid < 64) {
        sbt[tid] = bt[tid];
        sbv[tid] = bv[tid];
        wtl[tid] = Wt[tid * 65 + 64];
        sdiv[tid] = powf(10000.0f, -(float)(2 * (tid >> 1)) / 64.0f);
    }

    // ---- per-thread edge state + gather X (bf16 hi/lo split) ----
    int e = tid;
    bool act = e < cnt;
    int src = 0, dn = 0; float t = 0.0f;
    if (act) {
        int pe = list[off + e];
        src = ei[pe]; dn = ei[E + pe]; t = etime[pe];
    }
    {
        const float4* xr = (const float4*)(g_xn + (size_t)src * 64);
#pragma unroll
        for (int kk = 0; kk < 16; kk++) {
            float4 v = act ? xr[kk] : make_float4(0.f, 0.f, 0.f, 0.f);
            uint32_t h0, l0, h1, l1;
            split2(v.x, v.y, h0, l0);
            split2(v.z, v.w, h1, l1);
            uint32_t byte = (uint32_t)(e * 128 + kk * 8);
            uint32_t swo = SW128(byte);
            *(uint2*)(sb + OFF_AHI + swo) = make_uint2(h0, h1);
            *(uint2*)(sb + OFF_ALO + swo) = make_uint2(l0, l1);
        }
    }
    __syncthreads();

    uint32_t tmem;
    asm volatile("ld.shared.b32 %0, [%1];" : "=r"(tmem) : "r"(base_u + OFF_TMP));

    // ---- MMA1: xt_pre = X @ W1^T (hi/lo compensated) ----
    if (tid == 0) {
        FENCE_PROXY();
        uint64_t aH = mkdesc(base_u + OFF_AHI), aL = mkdesc(base_u + OFF_ALO);
        uint64_t bH = mkdesc(base_u + OFF_W1H), bL = mkdesc(base_u + OFF_W1L);
#pragma unroll
        for (int kc = 0; kc < 4; kc++) {
            mma_f16_ss(tmem, aH + kc * 2, bH + kc * 2, kc > 0 ? 1u : 0u);
            mma_f16_ss(tmem, aH + kc * 2, bL + kc * 2, 1u);
            mma_f16_ss(tmem, aL + kc * 2, bH + kc * 2, 1u);
        }
        TC_COMMIT(base_u + OFF_MBR);
    }

    mbar_wait(base_u + OFF_MBR, 0);
    TC_FENCE_AFTER();

    // ---- epilogue 1 ----
    uint32_t d1[64];
    TC_LD_X32(d1, tmem);
    TC_LD_X32(d1 + 32, tmem + 32);
    TC_WAIT_LD();

    float ex = 0.0f;
    {
        const float* qrow = qh + (size_t)dn * 64;
        float att = 0.0f;
        float t200 = t * 200.0f;
        uint32_t hbuf[4], lbuf[4];
#pragma unroll
        for (int m0 = 0; m0 < 64; m0 += 4) {
            float4 q4 = *(const float4*)(qrow + m0);
            float xt4[4];
#pragma unroll
            for (int j = 0; j < 4; j += 2) {
                int m = m0 + j;
                float sn, cc;
                sincosf(t200 * sdiv[m], &sn, &cc);
                float xe = __uint_as_float(d1[m])     + sbt[m]     + t * wtl[m];
                float xo = __uint_as_float(d1[m + 1]) + sbt[m + 1] + t * wtl[m + 1];
                xt4[j]     = gelu_erf(xe) + sn;
                xt4[j + 1] = gelu_erf(xo) + cc;
            }
            att += xt4[0] * q4.x + xt4[1] * q4.y + xt4[2] * q4.z + xt4[3] * q4.w;
            int half8 = (m0 & 4) ? 2 : 0;
            split2(xt4[0], xt4[1], hbuf[half8],     lbuf[half8]);
            split2(xt4[2], xt4[3], hbuf[half8 + 1], lbuf[half8 + 1]);
            if (m0 & 4) {
                uint32_t byte = (uint32_t)(e * 128 + (m0 - 4) * 2);
                uint32_t swo = SW128(byte);
                *(uint4*)(sb + OFF_AHI + swo) = make_uint4(hbuf[0], hbuf[1], hbuf[2], hbuf[3]);
                *(uint4*)(sb + OFF_ALO + swo) = make_uint4(lbuf[0], lbuf[1], lbuf[2], lbuf[3]);
            }
        }
        if (act) {
            ex = expf((att + cv[dn]) * 0.125f);
            atomicAdd(&g_den[dn], ex);
        }
    }
    __syncthreads();

    // ---- MMA2: v into TMEM cols 64..127 ----
    if (tid == 0) {
        FENCE_PROXY();
        uint64_t aH = mkdesc(base_u + OFF_AHI), aL = mkdesc(base_u + OFF_ALO);
        uint64_t bH = mkdesc(base_u + OFF_W2H), bL = mkdesc(base_u + OFF_W2L);
#pragma unroll
        for (int kc = 0; kc < 4; kc++) {
            mma_f16_ss(tmem + 64, aH + kc * 2, bH + kc * 2, kc > 0 ? 1u : 0u);
            mma_f16_ss(tmem + 64, aH + kc * 2, bL + kc * 2, 1u);
            mma_f16_ss(tmem + 64, aL + kc * 2, bH + kc * 2, 1u);
        }
        TC_COMMIT(base_u + OFF_MBR);
    }

    mbar_wait(base_u + OFF_MBR, 1);
    TC_FENCE_AFTER();

    uint32_t d2[64];
    TC_LD_X32(d2, tmem + 64);
    TC_LD_X32(d2 + 32, tmem + 96);
    TC_WAIT_LD();

    if (act) {
        float* dp = g_aggr + (size_t)dn * 64;
#pragma unroll
        for (int m0 = 0; m0 < 64; m0 += 4) {
            float v0 = (__uint_as_float(d2[m0])     + sbv[m0])     * ex;
            float v1 = (__uint_as_float(d2[m0 + 1]) + sbv[m0 + 1]) * ex;
            float v2 = (__uint_as_float(d2[m0 + 2]) + sbv[m0 + 2]) * ex;
            float v3 = (__uint_as_float(d2[m0 + 3]) + sbv[m0 + 3]) * ex;
            asm volatile("red.global.add.v4.f32 [%0], {%1, %2, %3, %4};"
                         :: "l"(dp + m0), "f"(v0), "f"(v1), "f"(v2), "f"(v3) : "memory");
        }
    }

    __syncthreads();
    if (tid == 0) MBAR_INVAL(base_u + OFF_MBR);
    __syncthreads();
    if (wid == 0) TC_DEALLOC(tmem, 128);

#else   // ---------------- fp32 fallback (non-'a' PTX pass only) -------------
    int e = tid;
    if (e < cnt) {
        int pe = list[off + e];
        int src = ei[pe], dn = ei[E + pe];
        float t = etime[pe];
        float t200 = t * 200.0f;
        const float* xrow = g_xn + (size_t)src * 64;
        float xt[64];
        float att = 0.0f;
        for (int m = 0; m < 64; m++) {
            float a = bt[m] + t * Wt[m * 65 + 64];
            for (int k = 0; k < 64; k++) a += xrow[k] * Wt[m * 65 + k];
            float dv = powf(10000.0f, -(float)(2 * (m / 2)) / 64.0f);
            float te = (m & 1) ? cosf(t200 * dv) : sinf(t200 * dv);
            xt[m] = gelu_erf(a) + te;
            att += xt[m] * qh[(size_t)dn * 64 + m];
        }
        float ex = expf((att + cv[dn]) * 0.125f);
        atomicAdd(&g_den[dn], ex);
        for (int m = 0; m < 64; m++) {
            float v = bv[m];
            for (int k = 0; k < 64; k++) v += xt[k] * Wv[m * 64 + k];
            atomicAdd(&g_aggr[(size_t)dn * 64 + m], ex * v);
        }
    }
#endif
}

// ---------------- kernel 5: epilogue (normalize by den) ----------------------
__global__ void final_kernel(const float* __restrict__ x, float* __restrict__ out, int N) {
    int i = blockIdx.x * blockDim.x + threadIdx.x;
    if (i < N * D) {
        float den = g_den[i >> 6];
        out[i] = x[i] + gelu_erf(g_aggr[i] / (den + 1e-16f));
    }
}

// ---------------- launch ------------------------------------------------------
extern "C" void kernel_launch(void* const* d_in, const int* in_sizes, int n_in,
                              void* d_out, int out_size) {
    const float* x     = (const float*)d_in[0];
    const int*   ei    = (const int*)  d_in[1];
    const float* etime = (const float*)d_in[2];
    const float* esame = (const float*)d_in[4];
    const float* lng   = (const float*)d_in[5];
    const float* lnb   = (const float*)d_in[6];
    const float* Wt    = (const float*)d_in[7];
    const float* bt    = (const float*)d_in[8];
    const float* Wq    = (const float*)d_in[9];
    const float* bq    = (const float*)d_in[10];
    const float* Wks   = (const float*)d_in[11];
    const float* bks   = (const float*)d_in[12];
    const float* Wkd   = (const float*)d_in[13];
    const float* bkd   = (const float*)d_in[14];
    const float* Wvs   = (const float*)d_in[15];
    const float* bvs   = (const float*)d_in[16];
    const float* Wvd   = (const float*)d_in[17];
    const float* bvd   = (const float*)d_in[18];
    float* out = (float*)d_out;

    int N = in_sizes[0] / D;
    int E = in_sizes[2];
    if (N > MAXN) N = MAXN;
    if (E > MAXE) E = MAXE;

    const int node_smem = NODE_SMEM_FLOATS * (int)sizeof(float);
    cudaFuncSetAttribute(node_kernel, cudaFuncAttributeMaxDynamicSharedMemorySize, node_smem);
    cudaFuncSetAttribute(edge_tc_kernel, cudaFuncAttributeMaxDynamicSharedMemorySize,
                         EDGE_SMEM_BYTES);

    init_kernel<<<(N * D + 255) / 256, 256>>>(N);
    partition_kernel<<<(E + 255) / 256, 256>>>(esame, E);
    fold_kernel<<<2, 256>>>(Wq, bq, Wks, bks, Wkd, bkd);
    node_kernel<<<(N + 127) / 128, 256, node_smem>>>(x, lng, lnb, N);
    edge_tc_kernel<<<(E + 127) / 128 + 1, 128, EDGE_SMEM_BYTES>>>(
        ei, etime, Wt, bt, Wvs, bvs, Wvd, bvd, E);
    final_kernel<<<(N * D + 255) / 256, 256>>>(x, out, N);
}

// round 9
// speedup vs baseline: 5.3994x; 1.1422x over previous
#include <cuda_runtime.h>
#include <cuda_bf16.h>
#include <math.h>
#include <stdint.h>

#define MAXN 50000
#define MAXE 800000
#define D 64
#define XS 130
#define WS 68

// tcgen05 is arch-SPECIFIC: only emit it in the sm_103a/'a'-target device pass.
#if !defined(__CUDA_ARCH__) || defined(__CUDA_ARCH_FEAT_SM103_ALL) || \
    defined(__CUDA_ARCH_FEAT_SM100_ALL) || defined(__CUDA_ARCH_SPECIFIC__) || \
    defined(__CUDA_ARCH_FAMILY_SPECIFIC__)
#define TC_OK 1
#else
#define TC_OK 0
#endif

typedef unsigned long long ull;

// ---------------- scratch ---------------------------------------------------
__device__ float g_xn  [MAXN * D];
__device__ float g_qh_s[MAXN * D];
__device__ float g_qh_d[MAXN * D];
__device__ float g_c_s [MAXN];
__device__ float g_c_d [MAXN];
__device__ float g_den [MAXN];
__device__ float g_aggr[MAXN * D];
__device__ int   g_perm_s[MAXE];
__device__ int   g_perm_d[MAXE];
__device__ int   g_cnt[2];
__device__ float g_MsT[4096];
__device__ float g_MdT[4096];
__device__ float g_ds[64], g_dd[64];
__device__ float g_us[64], g_ud[64];
__device__ float g_ec[2];

__device__ __forceinline__ float gelu_erf(float x) {
    return 0.5f * x * (1.0f + erff(x * 0.70710678118654752440f));
}
__device__ __forceinline__ ull dup2(float x) {
    ull r; asm("mov.b64 %0, {%1, %1};" : "=l"(r) : "f"(x)); return r;
}
__device__ __forceinline__ void ffma2(ull& d, ull a, ull b) {
    asm("fma.rn.f32x2 %0, %1, %2, %0;" : "+l"(d) : "l"(a), "l"(b));
}
__device__ __forceinline__ float2 unpk(ull v) {
    float2 f; asm("mov.b64 {%0, %1}, %2;" : "=f"(f.x), "=f"(f.y) : "l"(v)); return f;
}

// ---------------- bf16 pack helpers ------------------------------------------
__device__ __forceinline__ uint32_t packbf(float x0, float x1) {
    uint32_t r;
    asm("cvt.rn.bf16x2.f32 %0, %2, %1;" : "=r"(r) : "f"(x0), "f"(x1));
    return r;
}
__device__ __forceinline__ void split2(float x0, float x1, uint32_t& hp, uint32_t& lp) {
    hp = packbf(x0, x1);
    float h0 = __uint_as_float(hp << 16);
    float h1 = __uint_as_float(hp & 0xffff0000u);
    lp = packbf(x0 - h0, x1 - h1);
}

__device__ __forceinline__ uint32_t smem_u32(const void* p) {
    uint32_t a;
    asm("{ .reg .u64 t; cvta.to.shared.u64 t, %1; cvt.u32.u64 %0, t; }"
        : "=r"(a) : "l"(p));
    return a;
}
#define SW128(o) ((o) ^ (((o) >> 3) & 0x70))

__device__ __forceinline__ uint64_t mkdesc(uint32_t addr) {
    const uint64_t base = (2ull << 61) | (1ull << 46) | (64ull << 32) | (1ull << 16);
    return base | ((addr >> 4) & 0x3FFF);
}

// idesc kind::f16, bf16 x bf16 -> f32, M=128, N=64
#define MMA_IDESC 0x08100490u

#if TC_OK
__device__ __forceinline__ void mma_f16_ss(uint32_t d_tmem, uint64_t a_desc,
                                           uint64_t b_desc, uint32_t en) {
    asm volatile(
        "{\n\t"
        ".reg .pred p;\n\t"
        "setp.ne.u32 p, %5, 0;\n\t"
        "tcgen05.mma.cta_group::1.kind::f16 [%0], %1, %2, %3, {%4, %4, %4, %4}, p;\n\t"
        "}"
        :: "r"(d_tmem), "l"(a_desc), "l"(b_desc), "r"(MMA_IDESC), "r"(0u), "r"(en)
        : "memory");
}

#define TC_ALLOC(smem_addr, n) \
    asm volatile("tcgen05.alloc.cta_group::1.sync.aligned.shared::cta.b32 [%0], %1;" \
                 :: "r"(smem_addr), "r"((uint32_t)(n)) : "memory")
#define TC_RELINQ() \
    asm volatile("tcgen05.relinquish_alloc_permit.cta_group::1.sync.aligned;")
#define TC_DEALLOC(tmem, n) \
    asm volatile("tcgen05.dealloc.cta_group::1.sync.aligned.b32 %0, %1;" \
                 :: "r"(tmem), "r"((uint32_t)(n)))
#define TC_COMMIT(mbar) \
    asm volatile("tcgen05.commit.cta_group::1.mbarrier::arrive::one.shared::cluster.b64 [%0];" \
                 :: "r"(mbar) : "memory")
#define TC_FENCE_AFTER() \
    asm volatile("tcgen05.fence::after_thread_sync;" ::: "memory")
#define TC_WAIT_LD() \
    asm volatile("tcgen05.wait::ld.sync.aligned;" ::: "memory")
#define FENCE_PROXY() \
    asm volatile("fence.proxy.async.shared::cta;" ::: "memory")
#define MBAR_INIT(mbar, n) \
    asm volatile("mbarrier.init.shared.b64 [%0], %1;" :: "r"(mbar), "r"((uint32_t)(n)) : "memory")
#define MBAR_INVAL(mbar) \
    asm volatile("mbarrier.inval.shared.b64 [%0];" :: "r"(mbar) : "memory")

__device__ __forceinline__ void mbar_wait(uint32_t mbar, uint32_t parity) {
    asm volatile(
        "{\n\t"
        ".reg .pred P;\n\t"
        "WLOOP%=:\n\t"
        "mbarrier.try_wait.parity.acquire.cta.shared::cta.b64 P, [%0], %1, 0x989680;\n\t"
        "@P bra.uni WDONE%=;\n\t"
        "bra.uni WLOOP%=;\n\t"
        "WDONE%=:\n\t"
        "}"
        :: "r"(mbar), "r"(parity) : "memory");
}

#define TC_LD_X32(r, tmem_addr) \
    asm volatile( \
        "tcgen05.ld.sync.aligned.32x32b.x32.b32 " \
        "{%0, %1, %2, %3, %4, %5, %6, %7, " \
        " %8, %9, %10, %11, %12, %13, %14, %15, " \
        " %16, %17, %18, %19, %20, %21, %22, %23, " \
        " %24, %25, %26, %27, %28, %29, %30, %31}, [%32];" \
        : "=r"((r)[0]),  "=r"((r)[1]),  "=r"((r)[2]),  "=r"((r)[3]), \
          "=r"((r)[4]),  "=r"((r)[5]),  "=r"((r)[6]),  "=r"((r)[7]), \
          "=r"((r)[8]),  "=r"((r)[9]),  "=r"((r)[10]), "=r"((r)[11]), \
          "=r"((r)[12]), "=r"((r)[13]), "=r"((r)[14]), "=r"((r)[15]), \
          "=r"((r)[16]), "=r"((r)[17]), "=r"((r)[18]), "=r"((r)[19]), \
          "=r"((r)[20]), "=r"((r)[21]), "=r"((r)[22]), "=r"((r)[23]), \
          "=r"((r)[24]), "=r"((r)[25]), "=r"((r)[26]), "=r"((r)[27]), \
          "=r"((r)[28]), "=r"((r)[29]), "=r"((r)[30]), "=r"((r)[31]) \
        : "r"(tmem_addr))
#endif  // TC_OK

// ---------------- kernel 0: init --------------------------------------------
__global__ void init_kernel(int N) {
    int i = blockIdx.x * blockDim.x + threadIdx.x;
    if (i < N * D) g_aggr[i] = 0.0f;
    if (i < N) g_den[i] = 0.0f;
    if (i == 0) { g_cnt[0] = 0; g_cnt[1] = 0; }
}

// ---------------- kernel 0b: partition (warp-aggregated atomics) -------------
__global__ void partition_kernel(const float* __restrict__ esame, int E) {
    int e = blockIdx.x * blockDim.x + threadIdx.x;
    int lane = threadIdx.x & 31;
    bool act = e < E;
    float es = act ? esame[e] : 0.0f;
    bool s = act && (es >= 0.5f);
    bool d = act && (es < 0.5f);
    unsigned ms = __ballot_sync(0xffffffffu, s);
    unsigned md = __ballot_sync(0xffffffffu, d);
    int bs = 0, bd = 0;
    if (lane == 0) {
        if (ms) bs = atomicAdd(&g_cnt[0], __popc(ms));
        if (md) bd = atomicAdd(&g_cnt[1], __popc(md));
    }
    bs = __shfl_sync(0xffffffffu, bs, 0);
    bd = __shfl_sync(0xffffffffu, bd, 0);
    unsigned lower = (1u << lane) - 1u;
    if (s) g_perm_s[bs + __popc(ms & lower)] = e;
    if (d) g_perm_d[bd + __popc(md & lower)] = e;
}

// ---------------- kernel 0c: fold Wq into Wk space ---------------------------
__global__ __launch_bounds__(256) void fold_kernel(
    const float* __restrict__ Wq, const float* __restrict__ bq,
    const float* __restrict__ Wks, const float* __restrict__ bks,
    const float* __restrict__ Wkd, const float* __restrict__ bkd)
{
    int b = blockIdx.x;
    const float* Wk = b ? Wkd : Wks;
    const float* bk = b ? bkd : bks;
    float* MT   = b ? g_MdT : g_MsT;
    float* dvec = b ? g_dd : g_ds;
    float* uvec = b ? g_ud : g_us;

    __shared__ float sWq[4096], sWk[4096], sbq[64], sbk[64];
    int tid = threadIdx.x;
    for (int i = tid; i < 4096; i += 256) { sWq[i] = Wq[i]; sWk[i] = Wk[i]; }
    if (tid < 64) { sbq[tid] = bq[tid]; sbk[tid] = bk[tid]; }
    __syncthreads();
#pragma unroll
    for (int ii = 0; ii < 16; ii++) {
        int o = tid + ii * 256;
        int j = o >> 6, c = o & 63;
        float s = 0.0f;
#pragma unroll 8
        for (int m = 0; m < 64; m++) s += sWk[m * 64 + c] * sWq[m * 64 + j];
        MT[o] = s;
    }
    if (tid < 64) {
        float sd = 0.0f, su = 0.0f;
#pragma unroll 8
        for (int m = 0; m < 64; m++) {
            sd += sWk[m * 64 + tid] * sbq[m];
            su += sbk[m] * sWq[m * 64 + tid];
        }
        dvec[tid] = sd; uvec[tid] = su;
    }
    if (tid == 0) {
        float s = 0.0f;
        for (int m = 0; m < 64; m++) s += sbk[m] * sbq[m];
        g_ec[b] = s;
    }
}

// ---------------- kernel 1: layernorm + qh_s/qh_d/c --------------------------
#define NODE_SMEM_FLOATS (64*XS + 2*64*WS + 8*64)
__global__ __launch_bounds__(256, 2) void node_kernel(
    const float* __restrict__ x, const float* __restrict__ gamma,
    const float* __restrict__ beta, int N)
{
    extern __shared__ float ns[];
    float* XsT = ns;
    float* sMs = XsT + 64 * XS;
    float* sMd = sMs + 64 * WS;
    float* sg  = sMd + 64 * WS;
    float* sb  = sg + 64;
    float* sus = sb + 64;
    float* sud = sus + 64;
    float* sds = sud + 64;
    float* sdd = sds + 64;

    int tid = threadIdx.x;
    for (int i = tid; i < 4096; i += 256) {
        int j = i >> 6, c = i & 63;
        sMs[j * WS + c] = g_MsT[i];
        sMd[j * WS + c] = g_MdT[i];
    }
    if (tid < 64) {
        sg[tid] = gamma[tid]; sb[tid] = beta[tid];
        sus[tid] = g_us[tid]; sud[tid] = g_ud[tid];
        sds[tid] = g_ds[tid]; sdd[tid] = g_dd[tid];
    }
    __syncthreads();

    int n0 = blockIdx.x * 128;
    int cnt = min(128, N - n0);

    {
        int nl = tid >> 1, half = tid & 1;
        bool act = nl < cnt;
        int n = n0 + nl;
        float4 xv[8];
        float s = 0.0f, t = 0.0f;
        if (act) {
            const float4* xr = (const float4*)(x + (size_t)n * 64) + half * 8;
#pragma unroll
            for (int kk = 0; kk < 8; kk++) {
                xv[kk] = xr[kk];
                s += xv[kk].x + xv[kk].y + xv[kk].z + xv[kk].w;
                t += xv[kk].x * xv[kk].x + xv[kk].y * xv[kk].y
                   + xv[kk].z * xv[kk].z + xv[kk].w * xv[kk].w;
            }
        }
        s += __shfl_xor_sync(0xffffffffu, s, 1);
        t += __shfl_xor_sync(0xffffffffu, t, 1);
        float mu = s * (1.0f / 64.0f);
        float var = t * (1.0f / 64.0f) - mu * mu;
        float inv = rsqrtf(var + 1e-5f);
        float cs = 0.0f, cd = 0.0f;
        if (act) {
            float* gx = g_xn + (size_t)n * 64 + half * 32;
#pragma unroll
            for (int kk = 0; kk < 8; kk++) {
                int c0 = half * 32 + 4 * kk;
                float v[4] = {xv[kk].x, xv[kk].y, xv[kk].z, xv[kk].w};
                float xn4[4];
#pragma unroll
                for (int p = 0; p < 4; p++) {
                    int c = c0 + p;
                    float xn = (v[p] - mu) * inv * sg[c] + sb[c];
                    xn4[p] = xn;
                    XsT[c * XS + nl] = xn;
                    cs += xn * sus[c];
                    cd += xn * sud[c];
                }
                *(float4*)(gx + 4 * kk) = make_float4(xn4[0], xn4[1], xn4[2], xn4[3]);
            }
        }
        cs += __shfl_xor_sync(0xffffffffu, cs, 1);
        cd += __shfl_xor_sync(0xffffffffu, cd, 1);
        if (act && half == 0) {
            g_c_s[n] = cs + g_ec[0];
            g_c_d[n] = cd + g_ec[1];
        }
    }
    __syncthreads();

    int ty = tid >> 3, tx = tid & 7;
    int row0 = ty << 2, col0 = tx << 3;
#pragma unroll
    for (int pass = 0; pass < 2; pass++) {
        const float* M = pass ? sMd : sMs;
        const float* dv = pass ? sdd : sds;
        float* outp = pass ? g_qh_d : g_qh_s;
        ull acc[16];
        {
            const ull* dp = (const ull*)(dv + col0);
            ull w0 = dp[0], w1 = dp[1], w2 = dp[2], w3 = dp[3];
#pragma unroll
            for (int i = 0; i < 4; i++) {
                acc[i * 4] = w0; acc[i * 4 + 1] = w1; acc[i * 4 + 2] = w2; acc[i * 4 + 3] = w3;
            }
        }
#pragma unroll 4
        for (int k = 0; k < 64; k++) {
            const ull* axp = (const ull*)(XsT + k * XS + row0);
            float2 f01 = unpk(axp[0]), f23 = unpk(axp[1]);
            float aa[4] = {f01.x, f01.y, f23.x, f23.y};
            const ull* bp = (const ull*)(M + k * WS + col0);
            ull w0 = bp[0], w1 = bp[1], w2 = bp[2], w3 = bp[3];
#pragma unroll
            for (int i = 0; i < 4; i++) {
                ull ad = dup2(aa[i]);
                ffma2(acc[i * 4],     ad, w0);
                ffma2(acc[i * 4 + 1], ad, w1);
                ffma2(acc[i * 4 + 2], ad, w2);
                ffma2(acc[i * 4 + 3], ad, w3);
            }
        }
#pragma unroll
        for (int i = 0; i < 4; i++) {
            int nl = row0 + i;
            if (nl < cnt) {
                float* dp = outp + (size_t)(n0 + nl) * 64 + col0;
                float2 v0 = unpk(acc[i * 4]),     v1 = unpk(acc[i * 4 + 1]);
                float2 v2 = unpk(acc[i * 4 + 2]), v3 = unpk(acc[i * 4 + 3]);
                *(float4*)dp       = make_float4(v0.x, v0.y, v1.x, v1.y);
                *(float4*)(dp + 4) = make_float4(v2.x, v2.y, v3.x, v3.y);
            }
        }
    }
}

// ---------------- kernel 2: tensor-core edge kernel (persistent tiles) -------
#define OFF_AHI 0
#define OFF_ALO 16384
#define OFF_W1H 32768
#define OFF_W1L 40960
#define OFF_W2H 49152
#define OFF_W2L 57344
#define OFF_SBT 65536
#define OFF_SBV 65792
#define OFF_WTL 66048
#define OFF_SDV 66304
#define OFF_TMP 66560
#define OFF_MBR 66568
#define EDGE_SMEM_BYTES (1024 + 66576 + 48)

__global__ __launch_bounds__(128)
void edge_tc_kernel(
    const int* __restrict__ ei, const float* __restrict__ etime,
    const float* __restrict__ Wt,
    const float* __restrict__ bt,
    const float* __restrict__ Wvs, const float* __restrict__ bvs,
    const float* __restrict__ Wvd, const float* __restrict__ bvd,
    int E)
{
    int tid = threadIdx.x;
    int bid = blockIdx.x;

    int cs = g_cnt[0], cd = g_cnt[1];
    int ts = (cs + 127) >> 7;
    int td = (cd + 127) >> 7;
    int total = ts + td;

#if TC_OK
    extern __shared__ char dsm_raw[];
    uint32_t raw_u = smem_u32(dsm_raw);
    uint32_t base_u = (raw_u + 1023u) & ~1023u;
    char* sb = dsm_raw + (base_u - raw_u);
    int wid = tid >> 5;

    if (wid == 0) {
        TC_ALLOC(base_u + OFF_TMP, 128);
        TC_RELINQ();
    }
    if (tid == 0) MBAR_INIT(base_u + OFF_MBR, 1);

    float* sbt  = (float*)(sb + OFF_SBT);
    float* sbv  = (float*)(sb + OFF_SBV);
    float* wtl  = (float*)(sb + OFF_WTL);
    float* sdiv = (float*)(sb + OFF_SDV);

    // ---- one-time: W1 (= Wt, same-independent), bt, wtl, sdiv ----
    for (int i = tid; i < 2048; i += 128) {
        int m = i >> 5, k2 = (i & 31) * 2;
        uint32_t byte = (uint32_t)(m * 128 + k2 * 2);
        uint32_t swo = SW128(byte);
        uint32_t hp, lp;
        split2(Wt[m * 65 + k2], Wt[m * 65 + k2 + 1], hp, lp);
        *(uint32_t*)(sb + OFF_W1H + swo) = hp;
        *(uint32_t*)(sb + OFF_W1L + swo) = lp;
    }
    if (tid < 64) {
        sbt[tid] = bt[tid];
        wtl[tid] = Wt[tid * 65 + 64];
        sdiv[tid] = powf(10000.0f, -(float)(2 * (tid >> 1)) / 64.0f);
    }

    int cur_same = -1;
    int ph = 0;
    for (int ti = bid; ti < total; ti += gridDim.x) {
        int same, off, cnt;
        const int* list;
        if (ti < ts) {
            list = g_perm_s; off = ti << 7; cnt = min(128, cs - off); same = 1;
        } else {
            list = g_perm_d; off = (ti - ts) << 7; cnt = min(128, cd - off); same = 0;
        }
        const float* Wv = same ? Wvs : Wvd;
        const float* bv = same ? bvs : bvd;
        const float* qh = same ? g_qh_s : g_qh_d;
        const float* cv = same ? g_c_s  : g_c_d;

        __syncthreads();   // prev tile fully done with smem

        if (same != cur_same) {
            for (int i = tid; i < 2048; i += 128) {
                int m = i >> 5, k2 = (i & 31) * 2;
                uint32_t byte = (uint32_t)(m * 128 + k2 * 2);
                uint32_t swo = SW128(byte);
                uint32_t hp, lp;
                split2(Wv[m * 64 + k2], Wv[m * 64 + k2 + 1], hp, lp);
                *(uint32_t*)(sb + OFF_W2H + swo) = hp;
                *(uint32_t*)(sb + OFF_W2L + swo) = lp;
            }
            if (tid < 64) sbv[tid] = bv[tid];
            cur_same = same;
        }

        // ---- gather 128 edges ----
        int e = tid;
        bool act = e < cnt;
        int src = 0, dn = 0; float t = 0.0f;
        if (act) {
            int pe = list[off + e];
            src = ei[pe]; dn = ei[E + pe]; t = etime[pe];
        }
        {
            const float4* xr = (const float4*)(g_xn + (size_t)src * 64);
#pragma unroll
            for (int kk = 0; kk < 16; kk++) {
                float4 v = act ? xr[kk] : make_float4(0.f, 0.f, 0.f, 0.f);
                uint32_t h0, l0, h1, l1;
                split2(v.x, v.y, h0, l0);
                split2(v.z, v.w, h1, l1);
                uint32_t byte = (uint32_t)(e * 128 + kk * 8);
                uint32_t swo = SW128(byte);
                *(uint2*)(sb + OFF_AHI + swo) = make_uint2(h0, h1);
                *(uint2*)(sb + OFF_ALO + swo) = make_uint2(l0, l1);
            }
        }
        __syncthreads();

        uint32_t tmem;
        asm volatile("ld.shared.b32 %0, [%1];" : "=r"(tmem) : "r"(base_u + OFF_TMP));

        // ---- MMA1 ----
        if (tid == 0) {
            FENCE_PROXY();
            uint64_t aH = mkdesc(base_u + OFF_AHI), aL = mkdesc(base_u + OFF_ALO);
            uint64_t bH = mkdesc(base_u + OFF_W1H), bL = mkdesc(base_u + OFF_W1L);
#pragma unroll
            for (int kc = 0; kc < 4; kc++) {
                mma_f16_ss(tmem, aH + kc * 2, bH + kc * 2, kc > 0 ? 1u : 0u);
                mma_f16_ss(tmem, aH + kc * 2, bL + kc * 2, 1u);
                mma_f16_ss(tmem, aL + kc * 2, bH + kc * 2, 1u);
            }
            TC_COMMIT(base_u + OFF_MBR);
        }

        mbar_wait(base_u + OFF_MBR, ph); ph ^= 1;
        TC_FENCE_AFTER();

        // ---- epilogue 1 ----
        uint32_t d1[64];
        TC_LD_X32(d1, tmem);
        TC_LD_X32(d1 + 32, tmem + 32);
        TC_WAIT_LD();

        float ex = 0.0f;
        {
            const float* qrow = qh + (size_t)dn * 64;
            float att = 0.0f;
            float t200 = t * 200.0f;
            uint32_t hbuf[4], lbuf[4];
#pragma unroll
            for (int m0 = 0; m0 < 64; m0 += 4) {
                float4 q4 = *(const float4*)(qrow + m0);
                float xt4[4];
#pragma unroll
                for (int j = 0; j < 4; j += 2) {
                    int m = m0 + j;
                    float arg = t200 * sdiv[m];
                    float sn = __sinf(arg), cc = __cosf(arg);
                    float xe = __uint_as_float(d1[m])     + sbt[m]     + t * wtl[m];
                    float xo = __uint_as_float(d1[m + 1]) + sbt[m + 1] + t * wtl[m + 1];
                    xt4[j]     = gelu_erf(xe) + sn;
                    xt4[j + 1] = gelu_erf(xo) + cc;
                }
                att += xt4[0] * q4.x + xt4[1] * q4.y + xt4[2] * q4.z + xt4[3] * q4.w;
                int half8 = (m0 & 4) ? 2 : 0;
                split2(xt4[0], xt4[1], hbuf[half8],     lbuf[half8]);
                split2(xt4[2], xt4[3], hbuf[half8 + 1], lbuf[half8 + 1]);
                if (m0 & 4) {
                    uint32_t byte = (uint32_t)(e * 128 + (m0 - 4) * 2);
                    uint32_t swo = SW128(byte);
                    *(uint4*)(sb + OFF_AHI + swo) = make_uint4(hbuf[0], hbuf[1], hbuf[2], hbuf[3]);
                    *(uint4*)(sb + OFF_ALO + swo) = make_uint4(lbuf[0], lbuf[1], lbuf[2], lbuf[3]);
                }
            }
            if (act) {
                ex = __expf((att + cv[dn]) * 0.125f);
                atomicAdd(&g_den[dn], ex);
            }
        }
        __syncthreads();

        // ---- MMA2 ----
        if (tid == 0) {
            FENCE_PROXY();
            uint64_t aH = mkdesc(base_u + OFF_AHI), aL = mkdesc(base_u + OFF_ALO);
            uint64_t bH = mkdesc(base_u + OFF_W2H), bL = mkdesc(base_u + OFF_W2L);
#pragma unroll
            for (int kc = 0; kc < 4; kc++) {
                mma_f16_ss(tmem + 64, aH + kc * 2, bH + kc * 2, kc > 0 ? 1u : 0u);
                mma_f16_ss(tmem + 64, aH + kc * 2, bL + kc * 2, 1u);
                mma_f16_ss(tmem + 64, aL + kc * 2, bH + kc * 2, 1u);
            }
            TC_COMMIT(base_u + OFF_MBR);
        }

        mbar_wait(base_u + OFF_MBR, ph); ph ^= 1;
        TC_FENCE_AFTER();

        uint32_t d2[64];
        TC_LD_X32(d2, tmem + 64);
        TC_LD_X32(d2 + 32, tmem + 96);
        TC_WAIT_LD();

        if (act) {
            float* dp = g_aggr + (size_t)dn * 64;
#pragma unroll
            for (int m0 = 0; m0 < 64; m0 += 4) {
                float v0 = (__uint_as_float(d2[m0])     + sbv[m0])     * ex;
                float v1 = (__uint_as_float(d2[m0 + 1]) + sbv[m0 + 1]) * ex;
                float v2 = (__uint_as_float(d2[m0 + 2]) + sbv[m0 + 2]) * ex;
                float v3 = (__uint_as_float(d2[m0 + 3]) + sbv[m0 + 3]) * ex;
                asm volatile("red.global.add.v4.f32 [%0], {%1, %2, %3, %4};"
                             :: "l"(dp + m0), "f"(v0), "f"(v1), "f"(v2), "f"(v3) : "memory");
            }
        }
    }

    __syncthreads();
    if (tid == 0) MBAR_INVAL(base_u + OFF_MBR);
    __syncthreads();
    {
        uint32_t tmem;
        asm volatile("ld.shared.b32 %0, [%1];" : "=r"(tmem) : "r"(base_u + OFF_TMP));
        if (wid == 0) TC_DEALLOC(tmem, 128);
    }

#else   // ---------------- fp32 fallback (non-'a' PTX pass only) -------------
    for (int ti = bid; ti < total; ti += gridDim.x) {
        int same, off, cnt;
        const int* list;
        if (ti < ts) { list = g_perm_s; off = ti << 7; cnt = min(128, cs - off); same = 1; }
        else         { list = g_perm_d; off = (ti - ts) << 7; cnt = min(128, cd - off); same = 0; }
        const float* Wv = same ? Wvs : Wvd;
        const float* bv = same ? bvs : bvd;
        const float* qh = same ? g_qh_s : g_qh_d;
        const float* cv = same ? g_c_s  : g_c_d;
        int e = tid;
        if (e < cnt) {
            int pe = list[off + e];
            int src = ei[pe], dn = ei[E + pe];
            float t = etime[pe];
            float t200 = t * 200.0f;
            const float* xrow = g_xn + (size_t)src * 64;
            float xt[64];
            float att = 0.0f;
            for (int m = 0; m < 64; m++) {
                float a = bt[m] + t * Wt[m * 65 + 64];
                for (int k = 0; k < 64; k++) a += xrow[k] * Wt[m * 65 + k];
                float dv = powf(10000.0f, -(float)(2 * (m / 2)) / 64.0f);
                float te = (m & 1) ? cosf(t200 * dv) : sinf(t200 * dv);
                xt[m] = gelu_erf(a) + te;
                att += xt[m] * qh[(size_t)dn * 64 + m];
            }
            float ex = expf((att + cv[dn]) * 0.125f);
            atomicAdd(&g_den[dn], ex);
            for (int m = 0; m < 64; m++) {
                float v = bv[m];
                for (int k = 0; k < 64; k++) v += xt[k] * Wv[m * 64 + k];
                atomicAdd(&g_aggr[(size_t)dn * 64 + m], ex * v);
            }
        }
    }
#endif
}

// ---------------- kernel 5: epilogue (normalize by den) ----------------------
__global__ void final_kernel(const float* __restrict__ x, float* __restrict__ out, int N) {
    int i = blockIdx.x * blockDim.x + threadIdx.x;
    if (i < N * D) {
        float den = g_den[i >> 6];
        out[i] = x[i] + gelu_erf(g_aggr[i] / (den + 1e-16f));
    }
}

// ---------------- launch ------------------------------------------------------
extern "C" void kernel_launch(void* const* d_in, const int* in_sizes, int n_in,
                              void* d_out, int out_size) {
    const float* x     = (const float*)d_in[0];
    const int*   ei    = (const int*)  d_in[1];
    const float* etime = (const float*)d_in[2];
    const float* esame = (const float*)d_in[4];
    const float* lng   = (const float*)d_in[5];
    const float* lnb   = (const float*)d_in[6];
    const float* Wt    = (const float*)d_in[7];
    const float* bt    = (const float*)d_in[8];
    const float* Wq    = (const float*)d_in[9];
    const float* bq    = (const float*)d_in[10];
    const float* Wks   = (const float*)d_in[11];
    const float* bks   = (const float*)d_in[12];
    const float* Wkd   = (const float*)d_in[13];
    const float* bkd   = (const float*)d_in[14];
    const float* Wvs   = (const float*)d_in[15];
    const float* bvs   = (const float*)d_in[16];
    const float* Wvd   = (const float*)d_in[17];
    const float* bvd   = (const float*)d_in[18];
    float* out = (float*)d_out;

    int N = in_sizes[0] / D;
    int E = in_sizes[2];
    if (N > MAXN) N = MAXN;
    if (E > MAXE) E = MAXE;

    const int node_smem = NODE_SMEM_FLOATS * (int)sizeof(float);
    cudaFuncSetAttribute(node_kernel, cudaFuncAttributeMaxDynamicSharedMemorySize, node_smem);
    cudaFuncSetAttribute(edge_tc_kernel, cudaFuncAttributeMaxDynamicSharedMemorySize,
                         EDGE_SMEM_BYTES);

    // 2 tiles per CTA (grid-stride over tiles)
    int max_tiles = (E + 127) / 128 + 2;
    int edge_grid = (max_tiles + 1) / 2;

    init_kernel<<<(N * D + 255) / 256, 256>>>(N);
    partition_kernel<<<(E + 255) / 256, 256>>>(esame, E);
    fold_kernel<<<2, 256>>>(Wq, bq, Wks, bks, Wkd, bkd);
    node_kernel<<<(N + 127) / 128, 256, node_smem>>>(x, lng, lnb, N);
    edge_tc_kernel<<<edge_grid, 128, EDGE_SMEM_BYTES>>>(
        ei, etime, Wt, bt, Wvs, bvs, Wvd, bvd, E);
    final_kernel<<<(N * D + 255) / 256, 256>>>(x, out, N);
}